// round 5
// baseline (speedup 1.0000x reference)
#include <cuda_runtime.h>

typedef unsigned long long ULL;

// ---------------------------------------------------------------------------
// Packed fp32x2 FMA (sm_100+; FFMA2 in SASS — 2x FFMA throughput, PTX-only)
// ---------------------------------------------------------------------------
__device__ __forceinline__ void ffma2(ULL& d, ULL a, ULL b) {
    asm("fma.rn.f32x2 %0, %1, %2, %0;" : "+l"(d) : "l"(a), "l"(b));
}
__device__ __forceinline__ float2 unpack2(ULL v) {
    float2 r;
    asm("mov.b64 {%0, %1}, %2;" : "=f"(r.x), "=f"(r.y) : "l"(v));
    return r;
}

// ---------------------------------------------------------------------------
// Scratch (device globals — no allocation allowed). 16B-aligned because they
// are accessed through float2/float4 casts.
// ---------------------------------------------------------------------------
#define MAX_LOC 100000
#define MAX_EVT 200000

__device__ __align__(16) float g_evt[(size_t)MAX_EVT * 64];  // relu(evt_x @ W_evt + b)
__device__ __align__(16) float g_loc[(size_t)MAX_LOC * 64];  // relu(loc_x @ W_loc + b)
__device__ __align__(16) float g_msg[(size_t)MAX_LOC * 64];  // scatter-add accumulator
__device__ __align__(16) float g_cnt[MAX_LOC];               // edge counts
__device__ int g_idx32;                                      // 1 if edge_index is int32

// ---------------------------------------------------------------------------
// Detect edge_index dtype. JAX with x64 disabled silently emits int32 even
// though the reference asks for int64. Real int64 indices (< 1e5) always have
// a zero high word; int32 pairs read as int64 almost surely don't.
// Deterministic every launch -> graph-replay safe.
// ---------------------------------------------------------------------------
__global__ void detect_kernel(const long long* __restrict__ ei) {
    if (blockIdx.x == 0 && threadIdx.x == 0) {
        int is32 = 0;
        for (int i = 0; i < 256; i++) {
            ULL v = (ULL)ei[i];
            if (v >= 0x100000000ULL) { is32 = 1; break; }
        }
        g_idx32 = is32;
    }
}

// ---------------------------------------------------------------------------
// Zero the accumulators (must run every launch: deterministic replays)
// ---------------------------------------------------------------------------
__global__ void zero_kernel(int n /* = NL*64 */) {
    int i = blockIdx.x * blockDim.x + threadIdx.x;
    if (i < n) g_msg[i] = 0.0f;
    if (i < (n >> 6)) g_cnt[i] = 0.0f;
}

// ---------------------------------------------------------------------------
// Projection: out = relu(x @ W + b).   x:[N,128]  W:[128,64] (k-major)
// Block = 64 rows, 256 threads, each thread -> 4 rows x 4 cols.
// W staged transposed in SMEM as 16B units [col][k4], XOR-swizzled so the
// stride-4-col reads are conflict-free. Accumulators are fp32x2 pairs along K
// (horizontal add at the end): both FFMA2 operands come straight out of
// LDS.128 with zero packing movs.
// ---------------------------------------------------------------------------
__global__ __launch_bounds__(256) void proj_kernel(
    const float* __restrict__ x, const float* __restrict__ W,
    const float* __restrict__ bias, int which, int N)
{
    extern __shared__ __align__(16) char smem_raw[];
    ulonglong2 (*sWt)[32] = (ulonglong2 (*)[32])smem_raw;              // 64 cols x 32 units = 32 KB
    float (*sX)[132]      = (float (*)[132])(smem_raw + 64 * 32 * 16); // 64 rows x 132 (pad: 528B row, 16B-mult)

    float* out = which ? g_evt : g_loc;
    const int tid = threadIdx.x;
    const int rowBase = blockIdx.x * 64;

    // Stage W transposed + swizzled: float k of column `col` lives at
    // sWt[col][(k>>2) ^ ((col>>2)&7)], sub-slot k&3. Global read is coalesced.
    for (int i = tid; i < 128 * 64; i += 256) {
        int k = i >> 6, col = i & 63;
        float* p = (float*)&sWt[col][(k >> 2) ^ ((col >> 2) & 7)];
        p[k & 3] = W[i];
    }
    // Stage X (row-major, pad 132 so 16B reads stay aligned & spread).
    for (int i = tid; i < 64 * 128; i += 256) {
        int r = i >> 7, k = i & 127;
        int row = rowBase + r;
        sX[r][k] = (row < N) ? x[(long)row * 128 + k] : 0.0f;
    }
    __syncthreads();

    const int tc = tid & 15;        // col group 0..15
    const int c0 = tc * 4;          // 4 consecutive cols
    const int r0 = (tid >> 4) * 4;  // 4 consecutive rows

    ULL acc[4][4];
#pragma unroll
    for (int i = 0; i < 4; i++)
#pragma unroll
        for (int c = 0; c < 4; c++) acc[i][c] = 0ULL;

#pragma unroll 8
    for (int k4 = 0; k4 < 32; k4++) {
        const int uw = k4 ^ (tc & 7);   // same swizzle for all 4 cols of this thread
        ulonglong2 a0 = *(const ulonglong2*)&sX[r0 + 0][k4 * 4];
        ulonglong2 a1 = *(const ulonglong2*)&sX[r0 + 1][k4 * 4];
        ulonglong2 a2 = *(const ulonglong2*)&sX[r0 + 2][k4 * 4];
        ulonglong2 a3 = *(const ulonglong2*)&sX[r0 + 3][k4 * 4];
        ulonglong2 w0 = sWt[c0 + 0][uw];
        ulonglong2 w1 = sWt[c0 + 1][uw];
        ulonglong2 w2 = sWt[c0 + 2][uw];
        ulonglong2 w3 = sWt[c0 + 3][uw];
#define PROJ_STEP(av, i)                                            \
        ffma2(acc[i][0], av.x, w0.x); ffma2(acc[i][0], av.y, w0.y); \
        ffma2(acc[i][1], av.x, w1.x); ffma2(acc[i][1], av.y, w1.y); \
        ffma2(acc[i][2], av.x, w2.x); ffma2(acc[i][2], av.y, w2.y); \
        ffma2(acc[i][3], av.x, w3.x); ffma2(acc[i][3], av.y, w3.y);
        PROJ_STEP(a0, 0)
        PROJ_STEP(a1, 1)
        PROJ_STEP(a2, 2)
        PROJ_STEP(a3, 3)
#undef PROJ_STEP
    }

#pragma unroll
    for (int i = 0; i < 4; i++) {
        int row = rowBase + r0 + i;
        if (row < N) {
            float2 q0 = unpack2(acc[i][0]);
            float2 q1 = unpack2(acc[i][1]);
            float2 q2 = unpack2(acc[i][2]);
            float2 q3 = unpack2(acc[i][3]);
            float4 o;
            o.x = fmaxf(q0.x + q0.y + bias[c0 + 0], 0.0f);
            o.y = fmaxf(q1.x + q1.y + bias[c0 + 1], 0.0f);
            o.z = fmaxf(q2.x + q2.y + bias[c0 + 2], 0.0f);
            o.w = fmaxf(q3.x + q3.y + bias[c0 + 3], 0.0f);
            *(float4*)&out[(long)row * 64 + c0] = o;
        }
    }
}

// ---------------------------------------------------------------------------
// Edge scatter: one warp per edge. Each lane moves 2 floats (float2 gather +
// 2x RED.ADD). Lane 0 bumps the destination count. evt_h (51 MB) is
// L2-resident, so the random gather mostly hits L2. Dual-dtype index read +
// hard bounds guards (no wild address can ever leave this kernel).
// ---------------------------------------------------------------------------
__global__ void scatter_kernel(const long long* __restrict__ ei, int E, int NL)
{
    long gid = (long)blockIdx.x * blockDim.x + threadIdx.x;
    int e = (int)(gid >> 5);
    int lane = (int)(gid & 31);
    if (e >= E) return;

    int s, d;
    if (g_idx32) {
        const int* e32 = (const int*)ei;
        s = e32[e];                  // source (event) node
        d = e32[E + e];              // destination (location) node
    } else {
        s = (int)ei[e];
        d = (int)ei[(long)E + e];
    }
    if ((unsigned)s >= (unsigned)MAX_EVT || (unsigned)d >= (unsigned)NL) return;

    float2 v = *(const float2*)&g_evt[(long)s * 64 + lane * 2];
    float* mp = &g_msg[(long)d * 64 + lane * 2];
    atomicAdd(mp, v.x);
    atomicAdd(mp + 1, v.y);
    if (lane == 0) atomicAdd(&g_cnt[d], 1.0f);
}

// ---------------------------------------------------------------------------
// Fused SAGE + head. One warp per location row; each lane owns z-cols
// (lane, lane+32). Weights staged transposed in SMEM as 64-bit K-pairs
// (pad 33 -> conflict-free 64-bit LDS), so every FFMA2 operand pair is free.
// sAgg/sLoc are 16B-aligned because they are read through ULL casts.
// Head: lane t owns h_t, warp-shuffle reduction produces the logit.
// Persistent blocks amortize staging.
// ---------------------------------------------------------------------------
__global__ __launch_bounds__(256) void fused_kernel(
    const float* __restrict__ Wl, const float* __restrict__ bl,
    const float* __restrict__ Wr,
    const float* __restrict__ Wh1, const float* __restrict__ bh1,
    const float* __restrict__ Wh2, const float* __restrict__ bh2,
    float* __restrict__ out, int N)
{
    __shared__ ULL sWlT[64][33];   // [o][kp] = (Wl[2kp][o], Wl[2kp+1][o])
    __shared__ ULL sWrT[64][33];
    __shared__ ULL sH1T[32][33];   // [t][op] = (Wh1[2op][t], Wh1[2op+1][t])
    __shared__ float sbl[64], sbh1[32], swh2[32], sbh2;
    __shared__ __align__(16) float sAgg[8][64];  // reused as z buffer (ULL reads!)
    __shared__ __align__(16) float sLoc[8][64];

    const int tid = threadIdx.x;
    for (int i = tid; i < 64 * 64; i += 256) {
        int k = i >> 6, o = i & 63;
        ((float*)&sWlT[o][k >> 1])[k & 1] = Wl[i];
        ((float*)&sWrT[o][k >> 1])[k & 1] = Wr[i];
    }
    for (int i = tid; i < 64 * 32; i += 256) {
        int o = i >> 5, t = i & 31;
        ((float*)&sH1T[t][o >> 1])[o & 1] = Wh1[i];
    }
    if (tid < 64) sbl[tid] = bl[tid];
    if (tid < 32) { sbh1[tid] = bh1[tid]; swh2[tid] = Wh2[tid]; }
    if (tid == 0) sbh2 = bh2[0];
    __syncthreads();

    const int lane = tid & 31;
    const int r = tid >> 5;

    for (int row = blockIdx.x * 8 + r; row < N; row += gridDim.x * 8) {
        long base = (long)row * 64;
        float inv = 1.0f / fmaxf(g_cnt[row], 1.0f);
        sAgg[r][lane]      = g_msg[base + lane] * inv;
        sAgg[r][lane + 32] = g_msg[base + lane + 32] * inv;
        sLoc[r][lane]      = g_loc[base + lane];
        sLoc[r][lane + 32] = g_loc[base + lane + 32];
        __syncwarp();

        // z = relu(agg @ Wl + bl + loc @ Wr); lane owns cols (lane, lane+32)
        ULL acc0 = 0ULL, acc1 = 0ULL;
#pragma unroll 8
        for (int kp = 0; kp < 32; kp++) {
            ULL a2 = *(const ULL*)&sAgg[r][2 * kp];
            ULL l2 = *(const ULL*)&sLoc[r][2 * kp];
            ffma2(acc0, a2, sWlT[lane][kp]);
            ffma2(acc1, a2, sWlT[lane + 32][kp]);
            ffma2(acc0, l2, sWrT[lane][kp]);
            ffma2(acc1, l2, sWrT[lane + 32][kp]);
        }
        float2 p0 = unpack2(acc0), p1 = unpack2(acc1);
        float z0 = fmaxf(p0.x + p0.y + sbl[lane], 0.0f);
        float z1 = fmaxf(p1.x + p1.y + sbl[lane + 32], 0.0f);
        __syncwarp();                     // all lanes done reading sAgg
        sAgg[r][lane]      = z0;          // reuse sAgg as z buffer
        sAgg[r][lane + 32] = z1;
        __syncwarp();

        // head: h_t = relu(z @ Wh1 + bh1), logit = h @ Wh2 + bh2
        ULL hacc = 0ULL;
#pragma unroll 8
        for (int op = 0; op < 32; op++) {
            ULL z2 = *(const ULL*)&sAgg[r][2 * op];
            ffma2(hacc, z2, sH1T[lane][op]);
        }
        float2 hp = unpack2(hacc);
        float h = fmaxf(hp.x + hp.y + sbh1[lane], 0.0f);
        float part = h * swh2[lane];
#pragma unroll
        for (int off = 16; off; off >>= 1)
            part += __shfl_xor_sync(0xffffffffu, part, off);
        if (lane == 0) out[row] = part + sbh2;
        __syncwarp();                     // before next iteration rewrites sAgg
    }
}

// ---------------------------------------------------------------------------
// Launch: all default-stream, graph-capturable, no allocation, no sync.
// ---------------------------------------------------------------------------
extern "C" void kernel_launch(void* const* d_in, const int* in_sizes, int n_in,
                              void* d_out, int out_size)
{
    const float*     loc_x = (const float*)d_in[0];
    const float*     evt_x = (const float*)d_in[1];
    const long long* ei    = (const long long*)d_in[2];
    const float*     W_loc = (const float*)d_in[3];
    const float*     b_loc = (const float*)d_in[4];
    const float*     W_evt = (const float*)d_in[5];
    const float*     b_evt = (const float*)d_in[6];
    const float*     W_l   = (const float*)d_in[7];
    const float*     b_l   = (const float*)d_in[8];
    const float*     W_r   = (const float*)d_in[9];
    const float*     W_h1  = (const float*)d_in[10];
    const float*     b_h1  = (const float*)d_in[11];
    const float*     W_h2  = (const float*)d_in[12];
    const float*     b_h2  = (const float*)d_in[13];
    float* out = (float*)d_out;

    int NL = in_sizes[0] / 128;   // 100000
    int NE = in_sizes[1] / 128;   // 200000
    int E  = in_sizes[2] / 2;     // 1000000 (element count same for i32/i64)
    if (NL > MAX_LOC) NL = MAX_LOC;
    if (NE > MAX_EVT) NE = MAX_EVT;

    const int PROJ_SMEM = 64 * 32 * 16 + 64 * 132 * 4;  // 66560 B
    cudaFuncSetAttribute(proj_kernel,
                         cudaFuncAttributeMaxDynamicSharedMemorySize, PROJ_SMEM);

    detect_kernel<<<1, 32>>>(ei);
    zero_kernel<<<(NL * 64 + 255) / 256, 256>>>(NL * 64);
    proj_kernel<<<(NE + 63) / 64, 256, PROJ_SMEM>>>(evt_x, W_evt, b_evt, 1, NE);
    proj_kernel<<<(NL + 63) / 64, 256, PROJ_SMEM>>>(loc_x, W_loc, b_loc, 0, NL);

    long sc_threads = (long)E * 32;
    int sc_blocks = (int)((sc_threads + 255) / 256);
    scatter_kernel<<<sc_blocks, 256>>>(ei, E, NL);

    fused_kernel<<<592, 256>>>(W_l, b_l, W_r, W_h1, b_h1, W_h2, b_h2, out, NL);
}

// round 6
// speedup vs baseline: 1.4009x; 1.4009x over previous
#include <cuda_runtime.h>

typedef unsigned long long ULL;

// ---------------------------------------------------------------------------
// Packed fp32x2 FMA (sm_100+; FFMA2 in SASS — 2x FFMA throughput, PTX-only)
// ---------------------------------------------------------------------------
__device__ __forceinline__ void ffma2(ULL& d, ULL a, ULL b) {
    asm("fma.rn.f32x2 %0, %1, %2, %0;" : "+l"(d) : "l"(a), "l"(b));
}
__device__ __forceinline__ float2 unpack2(ULL v) {
    float2 r;
    asm("mov.b64 {%0, %1}, %2;" : "=f"(r.x), "=f"(r.y) : "l"(v));
    return r;
}

// ---------------------------------------------------------------------------
// Scratch (device globals — no allocation allowed). 16B-aligned (vector access)
// ---------------------------------------------------------------------------
#define MAX_LOC 100000
#define MAX_EVT 200000

__device__ __align__(16) float g_evt[(size_t)MAX_EVT * 64];
__device__ __align__(16) float g_loc[(size_t)MAX_LOC * 64];
__device__ __align__(16) float g_msg[(size_t)MAX_LOC * 64];
__device__ __align__(16) float g_cnt[MAX_LOC];
__device__ int g_idx32;   // 1 if edge_index buffer is int32 (JAX x64-off)

// ---------------------------------------------------------------------------
// Detect edge_index dtype (int32 vs int64); deterministic each launch.
// ---------------------------------------------------------------------------
__global__ void detect_kernel(const long long* __restrict__ ei) {
    if (blockIdx.x == 0 && threadIdx.x == 0) {
        int is32 = 0;
#pragma unroll 8
        for (int i = 0; i < 256; i++) {
            ULL v = (ULL)ei[i];
            if (v >= 0x100000000ULL) is32 = 1;
        }
        g_idx32 = is32;
    }
}

// ---------------------------------------------------------------------------
// Zero accumulators (vectorized; must run every launch for graph replays)
// ---------------------------------------------------------------------------
__global__ void zero_kernel(int n4 /* NL*16 */, int NL) {
    int i = blockIdx.x * blockDim.x + threadIdx.x;
    if (i < n4) ((float4*)g_msg)[i] = make_float4(0.f, 0.f, 0.f, 0.f);
    if (i < NL) g_cnt[i] = 0.0f;
}

// ---------------------------------------------------------------------------
// Projection: out = relu(x @ W + b).   x:[N,128]  W:[128,64] (k-major)
// 64 rows/block, 256 threads, thread -> 4 rows x 4 cols, FFMA2 inner loop
// with both operand pairs free from LDS.128 (see R2-R4 notes).
// ---------------------------------------------------------------------------
__global__ __launch_bounds__(256, 3) void proj_kernel(
    const float* __restrict__ x, const float* __restrict__ W,
    const float* __restrict__ bias, int which, int N)
{
    extern __shared__ __align__(16) char smem_raw[];
    ulonglong2 (*sWt)[32] = (ulonglong2 (*)[32])smem_raw;              // 32 KB
    float (*sX)[132]      = (float (*)[132])(smem_raw + 64 * 32 * 16);

    float* out = which ? g_evt : g_loc;
    const int tid = threadIdx.x;
    const int rowBase = blockIdx.x * 64;

    for (int i = tid; i < 128 * 64; i += 256) {
        int k = i >> 6, col = i & 63;
        float* p = (float*)&sWt[col][(k >> 2) ^ ((col >> 2) & 7)];
        p[k & 3] = W[i];
    }
    for (int i = tid; i < 64 * 128; i += 256) {
        int r = i >> 7, k = i & 127;
        int row = rowBase + r;
        sX[r][k] = (row < N) ? x[(long)row * 128 + k] : 0.0f;
    }
    __syncthreads();

    const int tc = tid & 15;
    const int c0 = tc * 4;
    const int r0 = (tid >> 4) * 4;

    ULL acc[4][4];
#pragma unroll
    for (int i = 0; i < 4; i++)
#pragma unroll
        for (int c = 0; c < 4; c++) acc[i][c] = 0ULL;

#pragma unroll 8
    for (int k4 = 0; k4 < 32; k4++) {
        const int uw = k4 ^ (tc & 7);
        ulonglong2 a0 = *(const ulonglong2*)&sX[r0 + 0][k4 * 4];
        ulonglong2 a1 = *(const ulonglong2*)&sX[r0 + 1][k4 * 4];
        ulonglong2 a2 = *(const ulonglong2*)&sX[r0 + 2][k4 * 4];
        ulonglong2 a3 = *(const ulonglong2*)&sX[r0 + 3][k4 * 4];
        ulonglong2 w0 = sWt[c0 + 0][uw];
        ulonglong2 w1 = sWt[c0 + 1][uw];
        ulonglong2 w2 = sWt[c0 + 2][uw];
        ulonglong2 w3 = sWt[c0 + 3][uw];
#define PROJ_STEP(av, i)                                            \
        ffma2(acc[i][0], av.x, w0.x); ffma2(acc[i][0], av.y, w0.y); \
        ffma2(acc[i][1], av.x, w1.x); ffma2(acc[i][1], av.y, w1.y); \
        ffma2(acc[i][2], av.x, w2.x); ffma2(acc[i][2], av.y, w2.y); \
        ffma2(acc[i][3], av.x, w3.x); ffma2(acc[i][3], av.y, w3.y);
        PROJ_STEP(a0, 0)
        PROJ_STEP(a1, 1)
        PROJ_STEP(a2, 2)
        PROJ_STEP(a3, 3)
#undef PROJ_STEP
    }

#pragma unroll
    for (int i = 0; i < 4; i++) {
        int row = rowBase + r0 + i;
        if (row < N) {
            float2 q0 = unpack2(acc[i][0]);
            float2 q1 = unpack2(acc[i][1]);
            float2 q2 = unpack2(acc[i][2]);
            float2 q3 = unpack2(acc[i][3]);
            float4 o;
            o.x = fmaxf(q0.x + q0.y + bias[c0 + 0], 0.0f);
            o.y = fmaxf(q1.x + q1.y + bias[c0 + 1], 0.0f);
            o.z = fmaxf(q2.x + q2.y + bias[c0 + 2], 0.0f);
            o.w = fmaxf(q3.x + q3.y + bias[c0 + 3], 0.0f);
            *(float4*)&out[(long)row * 64 + c0] = o;
        }
    }
}

// ---------------------------------------------------------------------------
// Edge scatter: 16 threads per edge, one float4 each. Vectorized float4
// atomicAdd (sm_90+ -> RED.E.ADD.F32.V4): 4x fewer L2 atomic ops than scalar.
// Gather is 256B contiguous per edge (coalesced), L2-resident.
// ---------------------------------------------------------------------------
__global__ void scatter_kernel(const long long* __restrict__ ei, int E, int NL)
{
    long gid = (long)blockIdx.x * blockDim.x + threadIdx.x;
    int e = (int)(gid >> 4);
    int q = (int)(gid & 15);
    if (e >= E) return;

    int s, d;
    if (g_idx32) {
        const int* e32 = (const int*)ei;
        s = e32[e];
        d = e32[E + e];
    } else {
        s = (int)ei[e];
        d = (int)ei[(long)E + e];
    }
    if ((unsigned)s >= (unsigned)MAX_EVT || (unsigned)d >= (unsigned)NL) return;

    float4 v = *(const float4*)&g_evt[(long)s * 64 + q * 4];
    atomicAdd((float4*)&g_msg[(long)d * 64 + q * 4], v);
    if (q == 0) atomicAdd(&g_cnt[d], 1.0f);
}

// ---------------------------------------------------------------------------
// Fused SAGE + head, 8 rows per warp per batch. The lane-indexed weight LDS
// (the expensive 2-wavefront reads) are amortized over 8 rows; row operands
// are warp-broadcast LDS (1 wavefront, ~free). Crossbar cost/row drops ~3x
// vs the 1-row version. Dynamic smem (75.5 KB) -> 3 blocks/SM.
// ---------------------------------------------------------------------------
#define FUSED_SMEM 75536

__global__ __launch_bounds__(256, 3) void fused_kernel(
    const float* __restrict__ Wl, const float* __restrict__ bl,
    const float* __restrict__ Wr,
    const float* __restrict__ Wh1, const float* __restrict__ bh1,
    const float* __restrict__ Wh2, const float* __restrict__ bh2,
    float* __restrict__ out, int N)
{
    extern __shared__ __align__(16) char sm[];
    ULL (*sWlT)[33]      = (ULL (*)[33])(sm);                 // 16896 B
    ULL (*sWrT)[33]      = (ULL (*)[33])(sm + 16896);         // 16896 B
    ULL (*sH1T)[33]      = (ULL (*)[33])(sm + 33792);         //  8448 B
    float* sbl           = (float*)(sm + 42240);              //   256 B
    float* sbh1          = (float*)(sm + 42496);              //   128 B
    float* swh2          = (float*)(sm + 42624);              //   128 B
    float* sbh2v         = (float*)(sm + 42752);              //    16 B
    float (*sAgg)[8][64] = (float (*)[8][64])(sm + 42768);    // 16384 B (16B aligned)
    float (*sLoc)[8][64] = (float (*)[8][64])(sm + 59152);    // 16384 B

    const int tid = threadIdx.x;
    for (int i = tid; i < 64 * 64; i += 256) {
        int k = i >> 6, o = i & 63;
        ((float*)&sWlT[o][k >> 1])[k & 1] = Wl[i];
        ((float*)&sWrT[o][k >> 1])[k & 1] = Wr[i];
    }
    for (int i = tid; i < 64 * 32; i += 256) {
        int o = i >> 5, t = i & 31;
        ((float*)&sH1T[t][o >> 1])[o & 1] = Wh1[i];
    }
    if (tid < 64) sbl[tid] = bl[tid];
    if (tid < 32) { sbh1[tid] = bh1[tid]; swh2[tid] = Wh2[tid]; }
    if (tid == 0) sbh2v[0] = bh2[0];
    __syncthreads();

    const int lane = tid & 31;
    const int w = tid >> 5;

    for (long base0 = (long)blockIdx.x * 64; base0 < N; base0 += (long)gridDim.x * 64) {
        const int base = (int)base0 + w * 8;   // this warp's 8 rows

        // Stage 8 rows of agg (msg/cnt) and loc: 128 float4s over 32 lanes.
#pragma unroll
        for (int i = 0; i < 4; i++) {
            int fi = i * 32 + lane;        // 0..127
            int j = fi >> 4;               // row within batch
            int c = (fi & 15) << 2;        // col (float4)
            int row = base + j;
            float4 mz = make_float4(0.f, 0.f, 0.f, 0.f), lz = mz;
            if (row < N) {
                float inv = 1.0f / fmaxf(g_cnt[row], 1.0f);
                float4 m = *(const float4*)&g_msg[(long)row * 64 + c];
                mz = make_float4(m.x * inv, m.y * inv, m.z * inv, m.w * inv);
                lz = *(const float4*)&g_loc[(long)row * 64 + c];
            }
            *(float4*)&sAgg[w][j][c] = mz;
            *(float4*)&sLoc[w][j][c] = lz;
        }
        __syncwarp();

        // z = relu(agg @ Wl + bl + loc @ Wr); lane owns cols (lane, lane+32),
        // 8 rows at once: weight reads amortized 8x.
        ULL acc0[8], acc1[8];
#pragma unroll
        for (int j = 0; j < 8; j++) { acc0[j] = 0ULL; acc1[j] = 0ULL; }
#pragma unroll 4
        for (int kp = 0; kp < 32; kp++) {
            ULL w0 = sWlT[lane][kp];
            ULL w1 = sWlT[lane + 32][kp];
            ULL w2 = sWrT[lane][kp];
            ULL w3 = sWrT[lane + 32][kp];
#pragma unroll
            for (int j = 0; j < 8; j++) {
                ULL a2 = *(const ULL*)&sAgg[w][j][2 * kp];   // broadcast
                ULL l2 = *(const ULL*)&sLoc[w][j][2 * kp];   // broadcast
                ffma2(acc0[j], a2, w0);
                ffma2(acc1[j], a2, w1);
                ffma2(acc0[j], l2, w2);
                ffma2(acc1[j], l2, w3);
            }
        }
        float zz0[8], zz1[8];
#pragma unroll
        for (int j = 0; j < 8; j++) {
            float2 p0 = unpack2(acc0[j]), p1 = unpack2(acc1[j]);
            zz0[j] = fmaxf(p0.x + p0.y + sbl[lane], 0.0f);
            zz1[j] = fmaxf(p1.x + p1.y + sbl[lane + 32], 0.0f);
        }
        __syncwarp();                       // everyone done reading sAgg
#pragma unroll
        for (int j = 0; j < 8; j++) {       // reuse sAgg as z buffer
            sAgg[w][j][lane]      = zz0[j];
            sAgg[w][j][lane + 32] = zz1[j];
        }
        __syncwarp();

        // head: h_t = relu(z @ Wh1 + bh1); logit = h @ Wh2 + bh2
        ULL hacc[8];
#pragma unroll
        for (int j = 0; j < 8; j++) hacc[j] = 0ULL;
#pragma unroll 4
        for (int op = 0; op < 32; op++) {
            ULL wv = sH1T[lane][op];
#pragma unroll
            for (int j = 0; j < 8; j++) {
                ULL z2 = *(const ULL*)&sAgg[w][j][2 * op];   // broadcast
                ffma2(hacc[j], z2, wv);
            }
        }
#pragma unroll
        for (int j = 0; j < 8; j++) {
            float2 hp = unpack2(hacc[j]);
            float h = fmaxf(hp.x + hp.y + sbh1[lane], 0.0f);
            float part = h * swh2[lane];
#pragma unroll
            for (int off = 16; off; off >>= 1)
                part += __shfl_xor_sync(0xffffffffu, part, off);
            int row = base + j;
            if (lane == 0 && row < N) out[row] = part + sbh2v[0];
        }
        __syncwarp();                       // before next batch rewrites sAgg
    }
}

// ---------------------------------------------------------------------------
// Launch: default stream, graph-capturable, no allocation, no sync.
// ---------------------------------------------------------------------------
extern "C" void kernel_launch(void* const* d_in, const int* in_sizes, int n_in,
                              void* d_out, int out_size)
{
    const float*     loc_x = (const float*)d_in[0];
    const float*     evt_x = (const float*)d_in[1];
    const long long* ei    = (const long long*)d_in[2];
    const float*     W_loc = (const float*)d_in[3];
    const float*     b_loc = (const float*)d_in[4];
    const float*     W_evt = (const float*)d_in[5];
    const float*     b_evt = (const float*)d_in[6];
    const float*     W_l   = (const float*)d_in[7];
    const float*     b_l   = (const float*)d_in[8];
    const float*     W_r   = (const float*)d_in[9];
    const float*     W_h1  = (const float*)d_in[10];
    const float*     b_h1  = (const float*)d_in[11];
    const float*     W_h2  = (const float*)d_in[12];
    const float*     b_h2  = (const float*)d_in[13];
    float* out = (float*)d_out;

    int NL = in_sizes[0] / 128;   // 100000
    int NE = in_sizes[1] / 128;   // 200000
    int E  = in_sizes[2] / 2;     // 1000000
    if (NL > MAX_LOC) NL = MAX_LOC;
    if (NE > MAX_EVT) NE = MAX_EVT;

    const int PROJ_SMEM = 64 * 32 * 16 + 64 * 132 * 4;  // 66560 B
    cudaFuncSetAttribute(proj_kernel,
                         cudaFuncAttributeMaxDynamicSharedMemorySize, PROJ_SMEM);
    cudaFuncSetAttribute(fused_kernel,
                         cudaFuncAttributeMaxDynamicSharedMemorySize, FUSED_SMEM);

    detect_kernel<<<1, 32>>>(ei);
    zero_kernel<<<(NL * 16 + 255) / 256, 256>>>(NL * 16, NL);
    proj_kernel<<<(NE + 63) / 64, 256, PROJ_SMEM>>>(evt_x, W_evt, b_evt, 1, NE);
    proj_kernel<<<(NL + 63) / 64, 256, PROJ_SMEM>>>(loc_x, W_loc, b_loc, 0, NL);

    long sc_threads = (long)E * 16;
    int sc_blocks = (int)((sc_threads + 255) / 256);
    scatter_kernel<<<sc_blocks, 256>>>(ei, E, NL);

    fused_kernel<<<444, 256, FUSED_SMEM>>>(W_l, b_l, W_r, W_h1, b_h1, W_h2, b_h2,
                                           out, NL);
}

// round 8
// speedup vs baseline: 1.6189x; 1.1556x over previous
#include <cuda_runtime.h>
#include <cuda_bf16.h>
#include <cstdint>

typedef unsigned long long ULL;

// ---------------------------------------------------------------------------
// Packed fp32x2 FMA (used by fused SAGE+head kernel)
// ---------------------------------------------------------------------------
__device__ __forceinline__ void ffma2(ULL& d, ULL a, ULL b) {
    asm("fma.rn.f32x2 %0, %1, %2, %0;" : "+l"(d) : "l"(a), "l"(b));
}
__device__ __forceinline__ float2 unpack2(ULL v) {
    float2 r;
    asm("mov.b64 {%0, %1}, %2;" : "=f"(r.x), "=f"(r.y) : "l"(v));
    return r;
}
__device__ __forceinline__ uint32_t smem_u32(const void* p) {
    uint32_t a;
    asm("{ .reg .u64 t; cvta.to.shared.u64 t, %1; cvt.u32.u64 %0, t; }"
        : "=r"(a) : "l"(p));
    return a;
}

// ---------------------------------------------------------------------------
// Scratch (device globals — no allocation allowed). 16B-aligned.
// ---------------------------------------------------------------------------
#define MAX_LOC 100000
#define MAX_EVT 200000

__device__ __align__(16) float g_evt[(size_t)MAX_EVT * 64];
__device__ __align__(16) float g_loc[(size_t)MAX_LOC * 64];
__device__ __align__(16) float g_msg[(size_t)MAX_LOC * 64];
__device__ __align__(16) float g_cnt[MAX_LOC];
__device__ int g_idx32;   // 1 if edge_index buffer is int32 (JAX x64-off)

// ---------------------------------------------------------------------------
// Detect edge_index dtype (int32 vs int64); deterministic each launch.
// ---------------------------------------------------------------------------
__global__ void detect_kernel(const long long* __restrict__ ei) {
    if (blockIdx.x == 0 && threadIdx.x == 0) {
        int is32 = 0;
#pragma unroll 8
        for (int i = 0; i < 256; i++) {
            ULL v = (ULL)ei[i];
            if (v >= 0x100000000ULL) is32 = 1;
        }
        g_idx32 = is32;
    }
}

// ---------------------------------------------------------------------------
// Zero accumulators (vectorized; must run every launch for graph replays)
// ---------------------------------------------------------------------------
__global__ void zero_kernel(int n4 /* NL*16 */, int NL) {
    int i = blockIdx.x * blockDim.x + threadIdx.x;
    if (i < n4) ((float4*)g_msg)[i] = make_float4(0.f, 0.f, 0.f, 0.f);
    if (i < NL) g_cnt[i] = 0.0f;
}

// ---------------------------------------------------------------------------
// Tensor-core projection via mma.sync (HMMA — works on base sm_103 target):
//   out = relu(x @ W + b), x:[N,128] fp32, W:[128,64].
// bf16 3-term split: X=X1+X2, W=W1+W2; Y ≈ X1W1 + X1W2 + X2W1 (fp32 accum;
// dropped X2W2 term ~2^-18 relative). 24 k16-steps total.
// SMEM: X1/X2 as [128 rows][128 k] bf16, W1/W2 transposed [64 n][128 k] bf16,
// all with 16B-unit XOR swizzle (unit ^= row&7) -> conflict-free ldmatrix.
// Warp tile 32x32: 2 m16-frags x 4 n8-frags, 8 mma per k16-step.
// ---------------------------------------------------------------------------
#define XH_OFF 256
#define XL_OFF (XH_OFF + 32768)
#define WH_OFF (XL_OFF + 32768)
#define WL_OFF (WH_OFF + 16384)
#define PROJ_SMEM (WL_OFF + 16384)   // 98560 B -> 2 CTAs/SM

__device__ __forceinline__ void ldsm_x4(uint32_t& r0, uint32_t& r1,
                                        uint32_t& r2, uint32_t& r3, uint32_t addr) {
    asm volatile("ldmatrix.sync.aligned.m8n8.x4.shared.b16 {%0,%1,%2,%3}, [%4];"
                 : "=r"(r0), "=r"(r1), "=r"(r2), "=r"(r3) : "r"(addr));
}
__device__ __forceinline__ void mma16816(float* c, const uint32_t* a,
                                         uint32_t b0, uint32_t b1) {
    asm volatile(
        "mma.sync.aligned.m16n8k16.row.col.f32.bf16.bf16.f32 "
        "{%0,%1,%2,%3}, {%4,%5,%6,%7}, {%8,%9}, {%0,%1,%2,%3};"
        : "+f"(c[0]), "+f"(c[1]), "+f"(c[2]), "+f"(c[3])
        : "r"(a[0]), "r"(a[1]), "r"(a[2]), "r"(a[3]), "r"(b0), "r"(b1));
}

__global__ __launch_bounds__(256, 2) void proj_mma_kernel(
    const float* __restrict__ x, const float* __restrict__ W,
    const float* __restrict__ bias, int which, int N)
{
    extern __shared__ __align__(16) char sm[];
    const uint32_t sb = smem_u32(sm);
    float* sbias = (float*)sm;                 // 256 B
    float* out = which ? g_evt : g_loc;

    const int tid = threadIdx.x;
    const int lane = tid & 31;
    const int w = tid >> 5;
    const int rowBase = blockIdx.x * 128;

    if (tid < 64) sbias[tid] = bias[tid];

    // --- Stage X -> bf16 hi/lo, swizzled [r][k] (rows of 256B = 16 units) ---
    for (int i = tid; i < 128 * 64; i += 256) {
        int r = i >> 6, kp = i & 63;           // kp = k-pair index
        int row = rowBase + r;
        if (row >= N) row = N - 1;             // clamp: valid read, store unused
        float2 v = *(const float2*)&x[(long)row * 128 + kp * 2];
        __nv_bfloat16 h0 = __float2bfloat16(v.x);
        __nv_bfloat16 h1 = __float2bfloat16(v.y);
        __nv_bfloat16 l0 = __float2bfloat16(v.x - __bfloat162float(h0));
        __nv_bfloat16 l1 = __float2bfloat16(v.y - __bfloat162float(h1));
        uint32_t hw = (uint32_t)__bfloat16_as_ushort(h0) |
                      ((uint32_t)__bfloat16_as_ushort(h1) << 16);
        uint32_t lw = (uint32_t)__bfloat16_as_ushort(l0) |
                      ((uint32_t)__bfloat16_as_ushort(l1) << 16);
        uint32_t off = (uint32_t)r * 256 + (((kp >> 2) ^ (r & 7)) * 16) + (kp & 3) * 4;
        *(uint32_t*)(sm + XH_OFF + off) = hw;
        *(uint32_t*)(sm + XL_OFF + off) = lw;
    }

    // --- Stage W^T -> bf16 hi/lo, swizzled [n][k] ---
    for (int i = tid; i < 64 * 64; i += 256) {
        int kp = i >> 6, n = i & 63;
        float w0 = W[(2 * kp) * 64 + n];
        float w1 = W[(2 * kp + 1) * 64 + n];
        __nv_bfloat16 h0 = __float2bfloat16(w0);
        __nv_bfloat16 h1 = __float2bfloat16(w1);
        __nv_bfloat16 l0 = __float2bfloat16(w0 - __bfloat162float(h0));
        __nv_bfloat16 l1 = __float2bfloat16(w1 - __bfloat162float(h1));
        uint32_t hw = (uint32_t)__bfloat16_as_ushort(h0) |
                      ((uint32_t)__bfloat16_as_ushort(h1) << 16);
        uint32_t lw = (uint32_t)__bfloat16_as_ushort(l0) |
                      ((uint32_t)__bfloat16_as_ushort(l1) << 16);
        uint32_t off = (uint32_t)n * 256 + (((kp >> 2) ^ (n & 7)) * 16) + (kp & 3) * 4;
        *(uint32_t*)(sm + WH_OFF + off) = hw;
        *(uint32_t*)(sm + WL_OFF + off) = lw;
    }
    __syncthreads();

    const int warpRow = (w >> 1) * 32;     // 4 row-groups
    const int warpCol = (w & 1) * 32;      // 2 col-groups

    float acc[2][4][4];
#pragma unroll
    for (int mi = 0; mi < 2; mi++)
#pragma unroll
        for (int nb = 0; nb < 4; nb++)
#pragma unroll
            for (int c = 0; c < 4; c++) acc[mi][nb][c] = 0.0f;

    // Precomputed per-lane address components
    const int aRow = warpRow + (lane & 15);        // + mi*16
    const int aKh  = lane >> 4;                    // k-half 0/1
    const int bN   = warpCol + ((lane >> 4) << 3) + (lane & 7);   // + ni2*16
    const int bKh  = (lane >> 3) & 1;

    for (int seg = 0; seg < 3; seg++) {
        const uint32_t aBase = sb + ((seg == 2) ? XL_OFF : XH_OFF);
        const uint32_t bBase = sb + ((seg == 1) ? WL_OFF : WH_OFF);
#pragma unroll
        for (int k16 = 0; k16 < 8; k16++) {
            uint32_t a[2][4], b[4][2];
#pragma unroll
            for (int mi = 0; mi < 2; mi++) {
                int r = aRow + mi * 16;
                uint32_t addr = aBase + (uint32_t)r * 256 +
                                (uint32_t)(((k16 * 2 + aKh) ^ (r & 7)) * 16);
                ldsm_x4(a[mi][0], a[mi][1], a[mi][2], a[mi][3], addr);
            }
#pragma unroll
            for (int ni2 = 0; ni2 < 2; ni2++) {
                int n = bN + ni2 * 16;
                uint32_t addr = bBase + (uint32_t)n * 256 +
                                (uint32_t)(((k16 * 2 + bKh) ^ (n & 7)) * 16);
                ldsm_x4(b[ni2 * 2][0], b[ni2 * 2][1],
                        b[ni2 * 2 + 1][0], b[ni2 * 2 + 1][1], addr);
            }
#pragma unroll
            for (int mi = 0; mi < 2; mi++)
#pragma unroll
                for (int nb = 0; nb < 4; nb++)
                    mma16816(acc[mi][nb], a[mi], b[nb][0], b[nb][1]);
        }
    }

    // --- Epilogue: bias + relu, float2 stores straight from fragments ---
#pragma unroll
    for (int mi = 0; mi < 2; mi++) {
#pragma unroll
        for (int part = 0; part < 2; part++) {
            int row = rowBase + warpRow + mi * 16 + (lane >> 2) + part * 8;
            if (row < N) {
                float* orow = out + (long)row * 64;
#pragma unroll
                for (int nb = 0; nb < 4; nb++) {
                    int col = warpCol + nb * 8 + (lane & 3) * 2;
                    float2 o;
                    o.x = fmaxf(acc[mi][nb][part * 2 + 0] + sbias[col], 0.0f);
                    o.y = fmaxf(acc[mi][nb][part * 2 + 1] + sbias[col + 1], 0.0f);
                    *(float2*)&orow[col] = o;
                }
            }
        }
    }
}

// ---------------------------------------------------------------------------
// Edge scatter: 16 threads/edge, float4 atomicAdd (RED.V4). Unchanged (R6).
// ---------------------------------------------------------------------------
__global__ void scatter_kernel(const long long* __restrict__ ei, int E, int NL)
{
    long gid = (long)blockIdx.x * blockDim.x + threadIdx.x;
    int e = (int)(gid >> 4);
    int q = (int)(gid & 15);
    if (e >= E) return;

    int s, d;
    if (g_idx32) {
        const int* e32 = (const int*)ei;
        s = e32[e];
        d = e32[E + e];
    } else {
        s = (int)ei[e];
        d = (int)ei[(long)E + e];
    }
    if ((unsigned)s >= (unsigned)MAX_EVT || (unsigned)d >= (unsigned)NL) return;

    float4 v = *(const float4*)&g_evt[(long)s * 64 + q * 4];
    atomicAdd((float4*)&g_msg[(long)d * 64 + q * 4], v);
    if (q == 0) atomicAdd(&g_cnt[d], 1.0f);
}

// ---------------------------------------------------------------------------
// Fused SAGE + head, 8 rows/warp per batch. Unchanged (R6).
// ---------------------------------------------------------------------------
#define FUSED_SMEM 75536

__global__ __launch_bounds__(256, 3) void fused_kernel(
    const float* __restrict__ Wl, const float* __restrict__ bl,
    const float* __restrict__ Wr,
    const float* __restrict__ Wh1, const float* __restrict__ bh1,
    const float* __restrict__ Wh2, const float* __restrict__ bh2,
    float* __restrict__ out, int N)
{
    extern __shared__ __align__(16) char smf[];
    ULL (*sWlT)[33]      = (ULL (*)[33])(smf);
    ULL (*sWrT)[33]      = (ULL (*)[33])(smf + 16896);
    ULL (*sH1T)[33]      = (ULL (*)[33])(smf + 33792);
    float* sbl           = (float*)(smf + 42240);
    float* sbh1          = (float*)(smf + 42496);
    float* swh2          = (float*)(smf + 42624);
    float* sbh2v         = (float*)(smf + 42752);
    float (*sAgg)[8][64] = (float (*)[8][64])(smf + 42768);
    float (*sLoc)[8][64] = (float (*)[8][64])(smf + 59152);

    const int tid = threadIdx.x;
    for (int i = tid; i < 64 * 64; i += 256) {
        int k = i >> 6, o = i & 63;
        ((float*)&sWlT[o][k >> 1])[k & 1] = Wl[i];
        ((float*)&sWrT[o][k >> 1])[k & 1] = Wr[i];
    }
    for (int i = tid; i < 64 * 32; i += 256) {
        int o = i >> 5, t = i & 31;
        ((float*)&sH1T[t][o >> 1])[o & 1] = Wh1[i];
    }
    if (tid < 64) sbl[tid] = bl[tid];
    if (tid < 32) { sbh1[tid] = bh1[tid]; swh2[tid] = Wh2[tid]; }
    if (tid == 0) sbh2v[0] = bh2[0];
    __syncthreads();

    const int lane = tid & 31;
    const int w = tid >> 5;

    for (long base0 = (long)blockIdx.x * 64; base0 < N; base0 += (long)gridDim.x * 64) {
        const int base = (int)base0 + w * 8;

#pragma unroll
        for (int i = 0; i < 4; i++) {
            int fi = i * 32 + lane;
            int j = fi >> 4;
            int c = (fi & 15) << 2;
            int row = base + j;
            float4 mz = make_float4(0.f, 0.f, 0.f, 0.f), lz = mz;
            if (row < N) {
                float inv = 1.0f / fmaxf(g_cnt[row], 1.0f);
                float4 m = *(const float4*)&g_msg[(long)row * 64 + c];
                mz = make_float4(m.x * inv, m.y * inv, m.z * inv, m.w * inv);
                lz = *(const float4*)&g_loc[(long)row * 64 + c];
            }
            *(float4*)&sAgg[w][j][c] = mz;
            *(float4*)&sLoc[w][j][c] = lz;
        }
        __syncwarp();

        ULL acc0[8], acc1[8];
#pragma unroll
        for (int j = 0; j < 8; j++) { acc0[j] = 0ULL; acc1[j] = 0ULL; }
#pragma unroll 4
        for (int kp = 0; kp < 32; kp++) {
            ULL w0 = sWlT[lane][kp];
            ULL w1 = sWlT[lane + 32][kp];
            ULL w2 = sWrT[lane][kp];
            ULL w3 = sWrT[lane + 32][kp];
#pragma unroll
            for (int j = 0; j < 8; j++) {
                ULL a2 = *(const ULL*)&sAgg[w][j][2 * kp];
                ULL l2 = *(const ULL*)&sLoc[w][j][2 * kp];
                ffma2(acc0[j], a2, w0);
                ffma2(acc1[j], a2, w1);
                ffma2(acc0[j], l2, w2);
                ffma2(acc1[j], l2, w3);
            }
        }
        float zz0[8], zz1[8];
#pragma unroll
        for (int j = 0; j < 8; j++) {
            float2 p0 = unpack2(acc0[j]), p1 = unpack2(acc1[j]);
            zz0[j] = fmaxf(p0.x + p0.y + sbl[lane], 0.0f);
            zz1[j] = fmaxf(p1.x + p1.y + sbl[lane + 32], 0.0f);
        }
        __syncwarp();
#pragma unroll
        for (int j = 0; j < 8; j++) {
            sAgg[w][j][lane]      = zz0[j];
            sAgg[w][j][lane + 32] = zz1[j];
        }
        __syncwarp();

        ULL hacc[8];
#pragma unroll
        for (int j = 0; j < 8; j++) hacc[j] = 0ULL;
#pragma unroll 4
        for (int op = 0; op < 32; op++) {
            ULL wv = sH1T[lane][op];
#pragma unroll
            for (int j = 0; j < 8; j++) {
                ULL z2 = *(const ULL*)&sAgg[w][j][2 * op];
                ffma2(hacc[j], z2, wv);
            }
        }
#pragma unroll
        for (int j = 0; j < 8; j++) {
            float2 hp = unpack2(hacc[j]);
            float h = fmaxf(hp.x + hp.y + sbh1[lane], 0.0f);
            float part = h * swh2[lane];
#pragma unroll
            for (int off = 16; off; off >>= 1)
                part += __shfl_xor_sync(0xffffffffu, part, off);
            int row = base + j;
            if (lane == 0 && row < N) out[row] = part + sbh2v[0];
        }
        __syncwarp();
    }
}

// ---------------------------------------------------------------------------
// Launch: default stream, graph-capturable, no allocation, no sync.
// ---------------------------------------------------------------------------
extern "C" void kernel_launch(void* const* d_in, const int* in_sizes, int n_in,
                              void* d_out, int out_size)
{
    const float*     loc_x = (const float*)d_in[0];
    const float*     evt_x = (const float*)d_in[1];
    const long long* ei    = (const long long*)d_in[2];
    const float*     W_loc = (const float*)d_in[3];
    const float*     b_loc = (const float*)d_in[4];
    const float*     W_evt = (const float*)d_in[5];
    const float*     b_evt = (const float*)d_in[6];
    const float*     W_l   = (const float*)d_in[7];
    const float*     b_l   = (const float*)d_in[8];
    const float*     W_r   = (const float*)d_in[9];
    const float*     W_h1  = (const float*)d_in[10];
    const float*     b_h1  = (const float*)d_in[11];
    const float*     W_h2  = (const float*)d_in[12];
    const float*     b_h2  = (const float*)d_in[13];
    float* out = (float*)d_out;

    int NL = in_sizes[0] / 128;   // 100000
    int NE = in_sizes[1] / 128;   // 200000
    int E  = in_sizes[2] / 2;     // 1000000
    if (NL > MAX_LOC) NL = MAX_LOC;
    if (NE > MAX_EVT) NE = MAX_EVT;

    cudaFuncSetAttribute(proj_mma_kernel,
                         cudaFuncAttributeMaxDynamicSharedMemorySize, PROJ_SMEM);
    cudaFuncSetAttribute(fused_kernel,
                         cudaFuncAttributeMaxDynamicSharedMemorySize, FUSED_SMEM);

    detect_kernel<<<1, 32>>>(ei);
    zero_kernel<<<(NL * 16 + 255) / 256, 256>>>(NL * 16, NL);
    proj_mma_kernel<<<(NE + 127) / 128, 256, PROJ_SMEM>>>(evt_x, W_evt, b_evt, 1, NE);
    proj_mma_kernel<<<(NL + 127) / 128, 256, PROJ_SMEM>>>(loc_x, W_loc, b_loc, 0, NL);

    long sc_threads = (long)E * 16;
    int sc_blocks = (int)((sc_threads + 255) / 256);
    scatter_kernel<<<sc_blocks, 256>>>(ei, E, NL);

    fused_kernel<<<444, 256, FUSED_SMEM>>>(W_l, b_l, W_r, W_h1, b_h1, W_h2, b_h2,
                                           out, NL);
}

// round 9
// speedup vs baseline: 1.8328x; 1.1321x over previous
#include <cuda_runtime.h>
#include <cuda_bf16.h>
#include <cstdint>

typedef unsigned long long ULL;

// ---------------------------------------------------------------------------
// Packed fp32x2 FMA (used by fused SAGE+head kernel)
// ---------------------------------------------------------------------------
__device__ __forceinline__ void ffma2(ULL& d, ULL a, ULL b) {
    asm("fma.rn.f32x2 %0, %1, %2, %0;" : "+l"(d) : "l"(a), "l"(b));
}
__device__ __forceinline__ float2 unpack2(ULL v) {
    float2 r;
    asm("mov.b64 {%0, %1}, %2;" : "=f"(r.x), "=f"(r.y) : "l"(v));
    return r;
}
__device__ __forceinline__ uint32_t smem_u32(const void* p) {
    uint32_t a;
    asm("{ .reg .u64 t; cvta.to.shared.u64 t, %1; cvt.u32.u64 %0, t; }"
        : "=r"(a) : "l"(p));
    return a;
}

// ---------------------------------------------------------------------------
// Scratch (device globals — no allocation allowed). 16B-aligned.
// ---------------------------------------------------------------------------
#define MAX_LOC 100000
#define MAX_EVT 200000

__device__ __align__(16) float g_evt[(size_t)MAX_EVT * 64];
__device__ __align__(16) float g_loc[(size_t)MAX_LOC * 64];
__device__ __align__(16) float g_msg[(size_t)MAX_LOC * 64];
__device__ __align__(16) float g_cnt[MAX_LOC];
__device__ int g_idx32;   // 1 if edge_index buffer is int32 (JAX x64-off)

// ---------------------------------------------------------------------------
// Detect edge_index dtype (int32 vs int64); deterministic each launch.
// ---------------------------------------------------------------------------
__global__ void detect_kernel(const long long* __restrict__ ei) {
    if (blockIdx.x == 0 && threadIdx.x == 0) {
        int is32 = 0;
#pragma unroll 8
        for (int i = 0; i < 256; i++) {
            ULL v = (ULL)ei[i];
            if (v >= 0x100000000ULL) is32 = 1;
        }
        g_idx32 = is32;
    }
}

// ---------------------------------------------------------------------------
// Zero accumulators (vectorized; must run every launch for graph replays)
// ---------------------------------------------------------------------------
__global__ void zero_kernel(int n4 /* NL*16 */, int NL) {
    int i = blockIdx.x * blockDim.x + threadIdx.x;
    if (i < n4) ((float4*)g_msg)[i] = make_float4(0.f, 0.f, 0.f, 0.f);
    if (i < NL) g_cnt[i] = 0.0f;
}

// ---------------------------------------------------------------------------
// Tensor-core projection via mma.sync, v3 (K-halved for occupancy):
//   out = relu(x @ W + b), x:[N,128] fp32, W:[128,64].
// bf16 3-term split (X1W1 + X1W2 + X2W1, fp32 accum; dropped term ~2^-18).
// One merged grid handles BOTH projections (block < nA -> loc, else evt).
// SMEM 64.3KB: X half hi/lo 16KB each (restaged per K-half), W hi/lo 16KB
// each (full K, staged once). 3 CTAs/SM (launch_bounds(256,3) -> <=84 regs).
// Staging moves whole 16B swizzle units: 2xLDG.128 -> cvt -> 2xSTS.128.
// ---------------------------------------------------------------------------
#define XH_OFF 256
#define XL_OFF (XH_OFF + 16384)
#define WH_OFF (XL_OFF + 16384)
#define WL_OFF (WH_OFF + 16384)
#define PROJ_SMEM (WL_OFF + 16384)   // 65792 B -> 3 CTAs/SM

__device__ __forceinline__ void ldsm_x4(uint32_t& r0, uint32_t& r1,
                                        uint32_t& r2, uint32_t& r3, uint32_t addr) {
    asm volatile("ldmatrix.sync.aligned.m8n8.x4.shared.b16 {%0,%1,%2,%3}, [%4];"
                 : "=r"(r0), "=r"(r1), "=r"(r2), "=r"(r3) : "r"(addr));
}
__device__ __forceinline__ void mma16816(float* c, const uint32_t* a,
                                         uint32_t b0, uint32_t b1) {
    asm volatile(
        "mma.sync.aligned.m16n8k16.row.col.f32.bf16.bf16.f32 "
        "{%0,%1,%2,%3}, {%4,%5,%6,%7}, {%8,%9}, {%0,%1,%2,%3};"
        : "+f"(c[0]), "+f"(c[1]), "+f"(c[2]), "+f"(c[3])
        : "r"(a[0]), "r"(a[1]), "r"(a[2]), "r"(a[3]), "r"(b0), "r"(b1));
}
__device__ __forceinline__ uint32_t bf16hi(float a, float b) {
    __nv_bfloat162 h = __float22bfloat162_rn(make_float2(a, b));
    return *(uint32_t*)&h;
}

__global__ __launch_bounds__(256, 3) void proj_mma_kernel(
    const float* __restrict__ xa, const float* __restrict__ Wa,
    const float* __restrict__ ba, int Na,
    const float* __restrict__ xb, const float* __restrict__ Wb,
    const float* __restrict__ bb, int Nb, int nA)
{
    extern __shared__ __align__(16) char sm[];
    const uint32_t sb = smem_u32(sm);
    float* sbias = (float*)sm;                 // 256 B

    const float *x, *W, *bias;
    float* out;
    int N, rowBase;
    if ((int)blockIdx.x < nA) {
        x = xa; W = Wa; bias = ba; out = g_loc; N = Na;
        rowBase = blockIdx.x * 128;
    } else {
        x = xb; W = Wb; bias = bb; out = g_evt; N = Nb;
        rowBase = (blockIdx.x - nA) * 128;
    }

    const int tid = threadIdx.x;
    const int lane = tid & 31;
    const int w = tid >> 5;

    if (tid < 64) sbias[tid] = bias[tid];

    // --- Stage W^T (full K) -> bf16 hi/lo, swizzled [n][k], 256B rows ---
    for (int i = tid; i < 64 * 64; i += 256) {
        int kp = i >> 6, n = i & 63;
        float w0 = W[(2 * kp) * 64 + n];
        float w1 = W[(2 * kp + 1) * 64 + n];
        __nv_bfloat16 h0 = __float2bfloat16(w0);
        __nv_bfloat16 h1 = __float2bfloat16(w1);
        uint32_t hw = (uint32_t)__bfloat16_as_ushort(h0) |
                      ((uint32_t)__bfloat16_as_ushort(h1) << 16);
        uint32_t lw = bf16hi(w0 - __bfloat162float(h0), w1 - __bfloat162float(h1));
        uint32_t off = (uint32_t)n * 256 + (((kp >> 2) ^ (n & 7)) * 16) + (kp & 3) * 4;
        *(uint32_t*)(sm + WH_OFF + off) = hw;
        *(uint32_t*)(sm + WL_OFF + off) = lw;
    }

    const int warpRow = (w >> 1) * 32;     // 4 row-groups
    const int warpCol = (w & 1) * 32;      // 2 col-groups

    float acc[2][4][4];
#pragma unroll
    for (int mi = 0; mi < 2; mi++)
#pragma unroll
        for (int nb = 0; nb < 4; nb++)
#pragma unroll
            for (int c = 0; c < 4; c++) acc[mi][nb][c] = 0.0f;

    // Per-lane fragment address components
    const int aRow = warpRow + (lane & 15);        // + mi*16
    const int aKh  = lane >> 4;                    // k-half of k16
    const int bN   = warpCol + ((lane >> 4) << 3) + (lane & 7);   // + ni2*16
    const int bKh  = (lane >> 3) & 1;

    for (int h = 0; h < 2; h++) {
        if (h) __syncthreads();   // previous half's ldmatrix reads are done

        // --- Stage X half h: thread moves 4 swizzle units (16B each) ---
#pragma unroll
        for (int j = 0; j < 4; j++) {
            int g = tid + 256 * j;          // unit id: 128 rows x 8 units
            int r = g >> 3, u = g & 7;
            int row = rowBase + r;
            if (row >= N) row = N - 1;      // clamp (valid read; store unused)
            const float4* src = (const float4*)&x[(long)row * 128 + h * 64 + u * 8];
            float4 v0 = src[0];
            float4 v1 = src[1];
            __nv_bfloat16 h0 = __float2bfloat16(v0.x), h1 = __float2bfloat16(v0.y);
            __nv_bfloat16 h2 = __float2bfloat16(v0.z), h3 = __float2bfloat16(v0.w);
            __nv_bfloat16 h4 = __float2bfloat16(v1.x), h5 = __float2bfloat16(v1.y);
            __nv_bfloat16 h6 = __float2bfloat16(v1.z), h7 = __float2bfloat16(v1.w);
            uint4 hiw, low;
            hiw.x = (uint32_t)__bfloat16_as_ushort(h0) | ((uint32_t)__bfloat16_as_ushort(h1) << 16);
            hiw.y = (uint32_t)__bfloat16_as_ushort(h2) | ((uint32_t)__bfloat16_as_ushort(h3) << 16);
            hiw.z = (uint32_t)__bfloat16_as_ushort(h4) | ((uint32_t)__bfloat16_as_ushort(h5) << 16);
            hiw.w = (uint32_t)__bfloat16_as_ushort(h6) | ((uint32_t)__bfloat16_as_ushort(h7) << 16);
            low.x = bf16hi(v0.x - __bfloat162float(h0), v0.y - __bfloat162float(h1));
            low.y = bf16hi(v0.z - __bfloat162float(h2), v0.w - __bfloat162float(h3));
            low.z = bf16hi(v1.x - __bfloat162float(h4), v1.y - __bfloat162float(h5));
            low.w = bf16hi(v1.z - __bfloat162float(h6), v1.w - __bfloat162float(h7));
            uint32_t off = (uint32_t)r * 128 + ((u ^ (r & 7)) * 16);
            *(uint4*)(sm + XH_OFF + off) = hiw;
            *(uint4*)(sm + XL_OFF + off) = low;
        }
        __syncthreads();

        // --- MMA: 3 segments x 4 k16-steps over this half ---
        for (int seg = 0; seg < 3; seg++) {
            const uint32_t aBase = sb + ((seg == 2) ? XL_OFF : XH_OFF);
            const uint32_t bBase = sb + ((seg == 1) ? WL_OFF : WH_OFF);
#pragma unroll
            for (int k16l = 0; k16l < 4; k16l++) {
                const int k16g = h * 4 + k16l;
                uint32_t a[2][4], b[4][2];
#pragma unroll
                for (int mi = 0; mi < 2; mi++) {
                    int r = aRow + mi * 16;
                    uint32_t addr = aBase + (uint32_t)r * 128 +
                                    (uint32_t)(((k16l * 2 + aKh) ^ (r & 7)) * 16);
                    ldsm_x4(a[mi][0], a[mi][1], a[mi][2], a[mi][3], addr);
                }
#pragma unroll
                for (int ni2 = 0; ni2 < 2; ni2++) {
                    int n = bN + ni2 * 16;
                    uint32_t addr = bBase + (uint32_t)n * 256 +
                                    (uint32_t)(((k16g * 2 + bKh) ^ (n & 7)) * 16);
                    ldsm_x4(b[ni2 * 2][0], b[ni2 * 2][1],
                            b[ni2 * 2 + 1][0], b[ni2 * 2 + 1][1], addr);
                }
#pragma unroll
                for (int mi = 0; mi < 2; mi++)
#pragma unroll
                    for (int nb = 0; nb < 4; nb++)
                        mma16816(acc[mi][nb], a[mi], b[nb][0], b[nb][1]);
            }
        }
    }

    // --- Epilogue: bias + relu, float2 stores straight from fragments ---
#pragma unroll
    for (int mi = 0; mi < 2; mi++) {
#pragma unroll
        for (int part = 0; part < 2; part++) {
            int row = rowBase + warpRow + mi * 16 + (lane >> 2) + part * 8;
            if (row < N) {
                float* orow = out + (long)row * 64;
#pragma unroll
                for (int nb = 0; nb < 4; nb++) {
                    int col = warpCol + nb * 8 + (lane & 3) * 2;
                    float2 o;
                    o.x = fmaxf(acc[mi][nb][part * 2 + 0] + sbias[col], 0.0f);
                    o.y = fmaxf(acc[mi][nb][part * 2 + 1] + sbias[col + 1], 0.0f);
                    *(float2*)&orow[col] = o;
                }
            }
        }
    }
}

// ---------------------------------------------------------------------------
// Edge scatter: 16 threads/edge, float4 atomicAdd (RED.V4). Unchanged (R6).
// ---------------------------------------------------------------------------
__global__ void scatter_kernel(const long long* __restrict__ ei, int E, int NL)
{
    long gid = (long)blockIdx.x * blockDim.x + threadIdx.x;
    int e = (int)(gid >> 4);
    int q = (int)(gid & 15);
    if (e >= E) return;

    int s, d;
    if (g_idx32) {
        const int* e32 = (const int*)ei;
        s = e32[e];
        d = e32[E + e];
    } else {
        s = (int)ei[e];
        d = (int)ei[(long)E + e];
    }
    if ((unsigned)s >= (unsigned)MAX_EVT || (unsigned)d >= (unsigned)NL) return;

    float4 v = *(const float4*)&g_evt[(long)s * 64 + q * 4];
    atomicAdd((float4*)&g_msg[(long)d * 64 + q * 4], v);
    if (q == 0) atomicAdd(&g_cnt[d], 1.0f);
}

// ---------------------------------------------------------------------------
// Fused SAGE + head, 8 rows/warp per batch. Unchanged (R6).
// ---------------------------------------------------------------------------
#define FUSED_SMEM 75536

__global__ __launch_bounds__(256, 3) void fused_kernel(
    const float* __restrict__ Wl, const float* __restrict__ bl,
    const float* __restrict__ Wr,
    const float* __restrict__ Wh1, const float* __restrict__ bh1,
    const float* __restrict__ Wh2, const float* __restrict__ bh2,
    float* __restrict__ out, int N)
{
    extern __shared__ __align__(16) char smf[];
    ULL (*sWlT)[33]      = (ULL (*)[33])(smf);
    ULL (*sWrT)[33]      = (ULL (*)[33])(smf + 16896);
    ULL (*sH1T)[33]      = (ULL (*)[33])(smf + 33792);
    float* sbl           = (float*)(smf + 42240);
    float* sbh1          = (float*)(smf + 42496);
    float* swh2          = (float*)(smf + 42624);
    float* sbh2v         = (float*)(smf + 42752);
    float (*sAgg)[8][64] = (float (*)[8][64])(smf + 42768);
    float (*sLoc)[8][64] = (float (*)[8][64])(smf + 59152);

    const int tid = threadIdx.x;
    for (int i = tid; i < 64 * 64; i += 256) {
        int k = i >> 6, o = i & 63;
        ((float*)&sWlT[o][k >> 1])[k & 1] = Wl[i];
        ((float*)&sWrT[o][k >> 1])[k & 1] = Wr[i];
    }
    for (int i = tid; i < 64 * 32; i += 256) {
        int o = i >> 5, t = i & 31;
        ((float*)&sH1T[t][o >> 1])[o & 1] = Wh1[i];
    }
    if (tid < 64) sbl[tid] = bl[tid];
    if (tid < 32) { sbh1[tid] = bh1[tid]; swh2[tid] = Wh2[tid]; }
    if (tid == 0) sbh2v[0] = bh2[0];
    __syncthreads();

    const int lane = tid & 31;
    const int w = tid >> 5;

    for (long base0 = (long)blockIdx.x * 64; base0 < N; base0 += (long)gridDim.x * 64) {
        const int base = (int)base0 + w * 8;

#pragma unroll
        for (int i = 0; i < 4; i++) {
            int fi = i * 32 + lane;
            int j = fi >> 4;
            int c = (fi & 15) << 2;
            int row = base + j;
            float4 mz = make_float4(0.f, 0.f, 0.f, 0.f), lz = mz;
            if (row < N) {
                float inv = 1.0f / fmaxf(g_cnt[row], 1.0f);
                float4 m = *(const float4*)&g_msg[(long)row * 64 + c];
                mz = make_float4(m.x * inv, m.y * inv, m.z * inv, m.w * inv);
                lz = *(const float4*)&g_loc[(long)row * 64 + c];
            }
            *(float4*)&sAgg[w][j][c] = mz;
            *(float4*)&sLoc[w][j][c] = lz;
        }
        __syncwarp();

        ULL acc0[8], acc1[8];
#pragma unroll
        for (int j = 0; j < 8; j++) { acc0[j] = 0ULL; acc1[j] = 0ULL; }
#pragma unroll 4
        for (int kp = 0; kp < 32; kp++) {
            ULL w0 = sWlT[lane][kp];
            ULL w1 = sWlT[lane + 32][kp];
            ULL w2 = sWrT[lane][kp];
            ULL w3 = sWrT[lane + 32][kp];
#pragma unroll
            for (int j = 0; j < 8; j++) {
                ULL a2 = *(const ULL*)&sAgg[w][j][2 * kp];
                ULL l2 = *(const ULL*)&sLoc[w][j][2 * kp];
                ffma2(acc0[j], a2, w0);
                ffma2(acc1[j], a2, w1);
                ffma2(acc0[j], l2, w2);
                ffma2(acc1[j], l2, w3);
            }
        }
        float zz0[8], zz1[8];
#pragma unroll
        for (int j = 0; j < 8; j++) {
            float2 p0 = unpack2(acc0[j]), p1 = unpack2(acc1[j]);
            zz0[j] = fmaxf(p0.x + p0.y + sbl[lane], 0.0f);
            zz1[j] = fmaxf(p1.x + p1.y + sbl[lane + 32], 0.0f);
        }
        __syncwarp();
#pragma unroll
        for (int j = 0; j < 8; j++) {
            sAgg[w][j][lane]      = zz0[j];
            sAgg[w][j][lane + 32] = zz1[j];
        }
        __syncwarp();

        ULL hacc[8];
#pragma unroll
        for (int j = 0; j < 8; j++) hacc[j] = 0ULL;
#pragma unroll 4
        for (int op = 0; op < 32; op++) {
            ULL wv = sH1T[lane][op];
#pragma unroll
            for (int j = 0; j < 8; j++) {
                ULL z2 = *(const ULL*)&sAgg[w][j][2 * op];
                ffma2(hacc[j], z2, wv);
            }
        }
#pragma unroll
        for (int j = 0; j < 8; j++) {
            float2 hp = unpack2(hacc[j]);
            float h = fmaxf(hp.x + hp.y + sbh1[lane], 0.0f);
            float part = h * swh2[lane];
#pragma unroll
            for (int off = 16; off; off >>= 1)
                part += __shfl_xor_sync(0xffffffffu, part, off);
            int row = base + j;
            if (lane == 0 && row < N) out[row] = part + sbh2v[0];
        }
        __syncwarp();
    }
}

// ---------------------------------------------------------------------------
// Launch: default stream, graph-capturable, no allocation, no sync.
// ---------------------------------------------------------------------------
extern "C" void kernel_launch(void* const* d_in, const int* in_sizes, int n_in,
                              void* d_out, int out_size)
{
    const float*     loc_x = (const float*)d_in[0];
    const float*     evt_x = (const float*)d_in[1];
    const long long* ei    = (const long long*)d_in[2];
    const float*     W_loc = (const float*)d_in[3];
    const float*     b_loc = (const float*)d_in[4];
    const float*     W_evt = (const float*)d_in[5];
    const float*     b_evt = (const float*)d_in[6];
    const float*     W_l   = (const float*)d_in[7];
    const float*     b_l   = (const float*)d_in[8];
    const float*     W_r   = (const float*)d_in[9];
    const float*     W_h1  = (const float*)d_in[10];
    const float*     b_h1  = (const float*)d_in[11];
    const float*     W_h2  = (const float*)d_in[12];
    const float*     b_h2  = (const float*)d_in[13];
    float* out = (float*)d_out;

    int NL = in_sizes[0] / 128;   // 100000
    int NE = in_sizes[1] / 128;   // 200000
    int E  = in_sizes[2] / 2;     // 1000000
    if (NL > MAX_LOC) NL = MAX_LOC;
    if (NE > MAX_EVT) NE = MAX_EVT;

    cudaFuncSetAttribute(proj_mma_kernel,
                         cudaFuncAttributeMaxDynamicSharedMemorySize, PROJ_SMEM);
    cudaFuncSetAttribute(fused_kernel,
                         cudaFuncAttributeMaxDynamicSharedMemorySize, FUSED_SMEM);

    detect_kernel<<<1, 32>>>(ei);
    zero_kernel<<<(NL * 16 + 255) / 256, 256>>>(NL * 16, NL);

    int nA = (NL + 127) / 128;            // 782 loc tiles
    int nB = (NE + 127) / 128;            // 1563 evt tiles
    proj_mma_kernel<<<nA + nB, 256, PROJ_SMEM>>>(loc_x, W_loc, b_loc, NL,
                                                 evt_x, W_evt, b_evt, NE, nA);

    long sc_threads = (long)E * 16;
    int sc_blocks = (int)((sc_threads + 255) / 256);
    scatter_kernel<<<sc_blocks, 256>>>(ei, E, NL);

    fused_kernel<<<444, 256, FUSED_SMEM>>>(W_l, b_l, W_r, W_h1, b_h1, W_h2, b_h2,
                                           out, NL);
}

// round 14
// speedup vs baseline: 1.9669x; 1.0732x over previous
#include <cuda_runtime.h>
#include <cuda_bf16.h>
#include <cstdint>

typedef unsigned long long ULL;

// ---------------------------------------------------------------------------
// Packed fp32x2 FMA (used by fused SAGE+head kernel)
// ---------------------------------------------------------------------------
__device__ __forceinline__ void ffma2(ULL& d, ULL a, ULL b) {
    asm("fma.rn.f32x2 %0, %1, %2, %0;" : "+l"(d) : "l"(a), "l"(b));
}
__device__ __forceinline__ float2 unpack2(ULL v) {
    float2 r;
    asm("mov.b64 {%0, %1}, %2;" : "=f"(r.x), "=f"(r.y) : "l"(v));
    return r;
}
__device__ __forceinline__ uint32_t smem_u32(const void* p) {
    uint32_t a;
    asm("{ .reg .u64 t; cvta.to.shared.u64 t, %1; cvt.u32.u64 %0, t; }"
        : "=r"(a) : "l"(p));
    return a;
}

// ---------------------------------------------------------------------------
// Scratch (device globals — no allocation allowed). 16B-aligned.
// ---------------------------------------------------------------------------
#define MAX_LOC 100000
#define MAX_EVT 200000

__device__ __align__(16) float g_evt[(size_t)MAX_EVT * 64];
__device__ __align__(16) float g_loc[(size_t)MAX_LOC * 64];
__device__ __align__(16) float g_msg[(size_t)MAX_LOC * 64];
__device__ __align__(16) float g_cnt[MAX_LOC];
__device__ int g_idx32;   // 1 if edge_index buffer is int32 (JAX x64-off)

// ---------------------------------------------------------------------------
// Zero accumulators + edge-index dtype detect (merged; one launch).
// Must run every launch: deterministic graph replays.
// ---------------------------------------------------------------------------
__global__ void zero_detect_kernel(const long long* __restrict__ ei,
                                   int n4 /* NL*16 */, int NL) {
    int i = blockIdx.x * blockDim.x + threadIdx.x;
    if (i < n4) ((float4*)g_msg)[i] = make_float4(0.f, 0.f, 0.f, 0.f);
    if (i < NL) g_cnt[i] = 0.0f;
    if (i == 0) {
        int is32 = 0;
#pragma unroll 8
        for (int k = 0; k < 256; k++) {
            ULL v = (ULL)ei[k];
            if (v >= 0x100000000ULL) is32 = 1;
        }
        g_idx32 = is32;
    }
}

// ---------------------------------------------------------------------------
// Tensor-core projection via mma.sync (unchanged from R9 — passing at 5e-6).
// ---------------------------------------------------------------------------
#define XH_OFF 256
#define XL_OFF (XH_OFF + 16384)
#define WH_OFF (XL_OFF + 16384)
#define WL_OFF (WH_OFF + 16384)
#define PROJ_SMEM (WL_OFF + 16384)   // 65792 B -> 3 CTAs/SM

__device__ __forceinline__ void ldsm_x4(uint32_t& r0, uint32_t& r1,
                                        uint32_t& r2, uint32_t& r3, uint32_t addr) {
    asm volatile("ldmatrix.sync.aligned.m8n8.x4.shared.b16 {%0,%1,%2,%3}, [%4];"
                 : "=r"(r0), "=r"(r1), "=r"(r2), "=r"(r3) : "r"(addr));
}
__device__ __forceinline__ void mma16816(float* c, const uint32_t* a,
                                         uint32_t b0, uint32_t b1) {
    asm volatile(
        "mma.sync.aligned.m16n8k16.row.col.f32.bf16.bf16.f32 "
        "{%0,%1,%2,%3}, {%4,%5,%6,%7}, {%8,%9}, {%0,%1,%2,%3};"
        : "+f"(c[0]), "+f"(c[1]), "+f"(c[2]), "+f"(c[3])
        : "r"(a[0]), "r"(a[1]), "r"(a[2]), "r"(a[3]), "r"(b0), "r"(b1));
}
__device__ __forceinline__ uint32_t bf16hi(float a, float b) {
    __nv_bfloat162 h = __float22bfloat162_rn(make_float2(a, b));
    return *(uint32_t*)&h;
}

__global__ __launch_bounds__(256, 3) void proj_mma_kernel(
    const float* __restrict__ xa, const float* __restrict__ Wa,
    const float* __restrict__ ba, int Na,
    const float* __restrict__ xb, const float* __restrict__ Wb,
    const float* __restrict__ bb, int Nb, int nA)
{
    extern __shared__ __align__(16) char sm[];
    const uint32_t sb = smem_u32(sm);
    float* sbias = (float*)sm;                 // 256 B

    const float *x, *W, *bias;
    float* out;
    int N, rowBase;
    if ((int)blockIdx.x < nA) {
        x = xa; W = Wa; bias = ba; out = g_loc; N = Na;
        rowBase = blockIdx.x * 128;
    } else {
        x = xb; W = Wb; bias = bb; out = g_evt; N = Nb;
        rowBase = (blockIdx.x - nA) * 128;
    }

    const int tid = threadIdx.x;
    const int lane = tid & 31;
    const int w = tid >> 5;

    if (tid < 64) sbias[tid] = bias[tid];

    // --- Stage W^T (full K) -> bf16 hi/lo, swizzled [n][k], 256B rows ---
    for (int i = tid; i < 64 * 64; i += 256) {
        int kp = i >> 6, n = i & 63;
        float w0 = W[(2 * kp) * 64 + n];
        float w1 = W[(2 * kp + 1) * 64 + n];
        __nv_bfloat16 h0 = __float2bfloat16(w0);
        __nv_bfloat16 h1 = __float2bfloat16(w1);
        uint32_t hw = (uint32_t)__bfloat16_as_ushort(h0) |
                      ((uint32_t)__bfloat16_as_ushort(h1) << 16);
        uint32_t lw = bf16hi(w0 - __bfloat162float(h0), w1 - __bfloat162float(h1));
        uint32_t off = (uint32_t)n * 256 + (((kp >> 2) ^ (n & 7)) * 16) + (kp & 3) * 4;
        *(uint32_t*)(sm + WH_OFF + off) = hw;
        *(uint32_t*)(sm + WL_OFF + off) = lw;
    }

    const int warpRow = (w >> 1) * 32;
    const int warpCol = (w & 1) * 32;

    float acc[2][4][4];
#pragma unroll
    for (int mi = 0; mi < 2; mi++)
#pragma unroll
        for (int nb = 0; nb < 4; nb++)
#pragma unroll
            for (int c = 0; c < 4; c++) acc[mi][nb][c] = 0.0f;

    const int aRow = warpRow + (lane & 15);
    const int aKh  = lane >> 4;
    const int bN   = warpCol + ((lane >> 4) << 3) + (lane & 7);
    const int bKh  = (lane >> 3) & 1;

    for (int h = 0; h < 2; h++) {
        if (h) __syncthreads();

        // --- Stage X half h: thread moves 4 swizzle units (16B each) ---
#pragma unroll
        for (int j = 0; j < 4; j++) {
            int g = tid + 256 * j;
            int r = g >> 3, u = g & 7;
            int row = rowBase + r;
            if (row >= N) row = N - 1;
            const float4* src = (const float4*)&x[(long)row * 128 + h * 64 + u * 8];
            float4 v0 = src[0];
            float4 v1 = src[1];
            __nv_bfloat16 h0 = __float2bfloat16(v0.x), h1 = __float2bfloat16(v0.y);
            __nv_bfloat16 h2 = __float2bfloat16(v0.z), h3 = __float2bfloat16(v0.w);
            __nv_bfloat16 h4 = __float2bfloat16(v1.x), h5 = __float2bfloat16(v1.y);
            __nv_bfloat16 h6 = __float2bfloat16(v1.z), h7 = __float2bfloat16(v1.w);
            uint4 hiw, low;
            hiw.x = (uint32_t)__bfloat16_as_ushort(h0) | ((uint32_t)__bfloat16_as_ushort(h1) << 16);
            hiw.y = (uint32_t)__bfloat16_as_ushort(h2) | ((uint32_t)__bfloat16_as_ushort(h3) << 16);
            hiw.z = (uint32_t)__bfloat16_as_ushort(h4) | ((uint32_t)__bfloat16_as_ushort(h5) << 16);
            hiw.w = (uint32_t)__bfloat16_as_ushort(h6) | ((uint32_t)__bfloat16_as_ushort(h7) << 16);
            low.x = bf16hi(v0.x - __bfloat162float(h0), v0.y - __bfloat162float(h1));
            low.y = bf16hi(v0.z - __bfloat162float(h2), v0.w - __bfloat162float(h3));
            low.z = bf16hi(v1.x - __bfloat162float(h4), v1.y - __bfloat162float(h5));
            low.w = bf16hi(v1.z - __bfloat162float(h6), v1.w - __bfloat162float(h7));
            uint32_t off = (uint32_t)r * 128 + ((u ^ (r & 7)) * 16);
            *(uint4*)(sm + XH_OFF + off) = hiw;
            *(uint4*)(sm + XL_OFF + off) = low;
        }
        __syncthreads();

        // --- MMA: 3 segments x 4 k16-steps over this half ---
        for (int seg = 0; seg < 3; seg++) {
            const uint32_t aBase = sb + ((seg == 2) ? XL_OFF : XH_OFF);
            const uint32_t bBase = sb + ((seg == 1) ? WL_OFF : WH_OFF);
#pragma unroll
            for (int k16l = 0; k16l < 4; k16l++) {
                const int k16g = h * 4 + k16l;
                uint32_t a[2][4], b[4][2];
#pragma unroll
                for (int mi = 0; mi < 2; mi++) {
                    int r = aRow + mi * 16;
                    uint32_t addr = aBase + (uint32_t)r * 128 +
                                    (uint32_t)(((k16l * 2 + aKh) ^ (r & 7)) * 16);
                    ldsm_x4(a[mi][0], a[mi][1], a[mi][2], a[mi][3], addr);
                }
#pragma unroll
                for (int ni2 = 0; ni2 < 2; ni2++) {
                    int n = bN + ni2 * 16;
                    uint32_t addr = bBase + (uint32_t)n * 256 +
                                    (uint32_t)(((k16g * 2 + bKh) ^ (n & 7)) * 16);
                    ldsm_x4(b[ni2 * 2][0], b[ni2 * 2][1],
                            b[ni2 * 2 + 1][0], b[ni2 * 2 + 1][1], addr);
                }
#pragma unroll
                for (int mi = 0; mi < 2; mi++)
#pragma unroll
                    for (int nb = 0; nb < 4; nb++)
                        mma16816(acc[mi][nb], a[mi], b[nb][0], b[nb][1]);
            }
        }
    }

    // --- Epilogue ---
#pragma unroll
    for (int mi = 0; mi < 2; mi++) {
#pragma unroll
        for (int part = 0; part < 2; part++) {
            int row = rowBase + warpRow + mi * 16 + (lane >> 2) + part * 8;
            if (row < N) {
                float* orow = out + (long)row * 64;
#pragma unroll
                for (int nb = 0; nb < 4; nb++) {
                    int col = warpCol + nb * 8 + (lane & 3) * 2;
                    float2 o;
                    o.x = fmaxf(acc[mi][nb][part * 2 + 0] + sbias[col], 0.0f);
                    o.y = fmaxf(acc[mi][nb][part * 2 + 1] + sbias[col + 1], 0.0f);
                    *(float2*)&orow[col] = o;
                }
            }
        }
    }
}

// ---------------------------------------------------------------------------
// Edge scatter v3: 4 edges per thread, front-batched. 16 threads cover the
// 64 floats of each edge (float4 per thread). All 4 gather LDG.128s issue
// before any RED.128, quadrupling per-thread MLP at identical traffic —
// pushes LTS utilization up from the measured 50%.
// ---------------------------------------------------------------------------
__global__ void scatter_kernel(const long long* __restrict__ ei, int E, int NL)
{
    long gid = (long)blockIdx.x * blockDim.x + threadIdx.x;
    int g4 = (int)(gid >> 4);        // group of 4 consecutive edges
    int q  = (int)(gid & 15);
    int e0 = g4 * 4;
    if (e0 >= E) return;
    const int idx32 = g_idx32;
    const int ne = (E - e0 < 4) ? (E - e0) : 4;

    int s[4], d[4];
#pragma unroll
    for (int j = 0; j < 4; j++) {
        int e = e0 + ((j < ne) ? j : 0);
        if (idx32) {
            const int* e32 = (const int*)ei;
            s[j] = e32[e];
            d[j] = e32[E + e];
        } else {
            s[j] = (int)ei[e];
            d[j] = (int)ei[(long)E + e];
        }
    }

    bool ok[4];
    float4 v[4];
#pragma unroll
    for (int j = 0; j < 4; j++) {
        ok[j] = (j < ne) && (unsigned)s[j] < (unsigned)MAX_EVT &&
                (unsigned)d[j] < (unsigned)NL;
        v[j] = ok[j] ? *(const float4*)&g_evt[(long)s[j] * 64 + q * 4]
                     : make_float4(0.f, 0.f, 0.f, 0.f);
    }
#pragma unroll
    for (int j = 0; j < 4; j++) {
        if (ok[j]) {
            atomicAdd((float4*)&g_msg[(long)d[j] * 64 + q * 4], v[j]);
            if (q == 0) atomicAdd(&g_cnt[d[j]], 1.0f);
        }
    }
}

// ---------------------------------------------------------------------------
// Fused SAGE + head, 8 rows/warp per batch. Unchanged (R9).
// ---------------------------------------------------------------------------
#define FUSED_SMEM 75536

__global__ __launch_bounds__(256, 3) void fused_kernel(
    const float* __restrict__ Wl, const float* __restrict__ bl,
    const float* __restrict__ Wr,
    const float* __restrict__ Wh1, const float* __restrict__ bh1,
    const float* __restrict__ Wh2, const float* __restrict__ bh2,
    float* __restrict__ out, int N)
{
    extern __shared__ __align__(16) char smf[];
    ULL (*sWlT)[33]      = (ULL (*)[33])(smf);
    ULL (*sWrT)[33]      = (ULL (*)[33])(smf + 16896);
    ULL (*sH1T)[33]      = (ULL (*)[33])(smf + 33792);
    float* sbl           = (float*)(smf + 42240);
    float* sbh1          = (float*)(smf + 42496);
    float* swh2          = (float*)(smf + 42624);
    float* sbh2v         = (float*)(smf + 42752);
    float (*sAgg)[8][64] = (float (*)[8][64])(smf + 42768);
    float (*sLoc)[8][64] = (float (*)[8][64])(smf + 59152);

    const int tid = threadIdx.x;
    for (int i = tid; i < 64 * 64; i += 256) {
        int k = i >> 6, o = i & 63;
        ((float*)&sWlT[o][k >> 1])[k & 1] = Wl[i];
        ((float*)&sWrT[o][k >> 1])[k & 1] = Wr[i];
    }
    for (int i = tid; i < 64 * 32; i += 256) {
        int o = i >> 5, t = i & 31;
        ((float*)&sH1T[t][o >> 1])[o & 1] = Wh1[i];
    }
    if (tid < 64) sbl[tid] = bl[tid];
    if (tid < 32) { sbh1[tid] = bh1[tid]; swh2[tid] = Wh2[tid]; }
    if (tid == 0) sbh2v[0] = bh2[0];
    __syncthreads();

    const int lane = tid & 31;
    const int w = tid >> 5;

    for (long base0 = (long)blockIdx.x * 64; base0 < N; base0 += (long)gridDim.x * 64) {
        const int base = (int)base0 + w * 8;

#pragma unroll
        for (int i = 0; i < 4; i++) {
            int fi = i * 32 + lane;
            int j = fi >> 4;
            int c = (fi & 15) << 2;
            int row = base + j;
            float4 mz = make_float4(0.f, 0.f, 0.f, 0.f), lz = mz;
            if (row < N) {
                float inv = 1.0f / fmaxf(g_cnt[row], 1.0f);
                float4 m = *(const float4*)&g_msg[(long)row * 64 + c];
                mz = make_float4(m.x * inv, m.y * inv, m.z * inv, m.w * inv);
                lz = *(const float4*)&g_loc[(long)row * 64 + c];
            }
            *(float4*)&sAgg[w][j][c] = mz;
            *(float4*)&sLoc[w][j][c] = lz;
        }
        __syncwarp();

        ULL acc0[8], acc1[8];
#pragma unroll
        for (int j = 0; j < 8; j++) { acc0[j] = 0ULL; acc1[j] = 0ULL; }
#pragma unroll 4
        for (int kp = 0; kp < 32; kp++) {
            ULL w0 = sWlT[lane][kp];
            ULL w1 = sWlT[lane + 32][kp];
            ULL w2 = sWrT[lane][kp];
            ULL w3 = sWrT[lane + 32][kp];
#pragma unroll
            for (int j = 0; j < 8; j++) {
                ULL a2 = *(const ULL*)&sAgg[w][j][2 * kp];
                ULL l2 = *(const ULL*)&sLoc[w][j][2 * kp];
                ffma2(acc0[j], a2, w0);
                ffma2(acc1[j], a2, w1);
                ffma2(acc0[j], l2, w2);
                ffma2(acc1[j], l2, w3);
            }
        }
        float zz0[8], zz1[8];
#pragma unroll
        for (int j = 0; j < 8; j++) {
            float2 p0 = unpack2(acc0[j]), p1 = unpack2(acc1[j]);
            zz0[j] = fmaxf(p0.x + p0.y + sbl[lane], 0.0f);
            zz1[j] = fmaxf(p1.x + p1.y + sbl[lane + 32], 0.0f);
        }
        __syncwarp();
#pragma unroll
        for (int j = 0; j < 8; j++) {
            sAgg[w][j][lane]      = zz0[j];
            sAgg[w][j][lane + 32] = zz1[j];
        }
        __syncwarp();

        ULL hacc[8];
#pragma unroll
        for (int j = 0; j < 8; j++) hacc[j] = 0ULL;
#pragma unroll 4
        for (int op = 0; op < 32; op++) {
            ULL wv = sH1T[lane][op];
#pragma unroll
            for (int j = 0; j < 8; j++) {
                ULL z2 = *(const ULL*)&sAgg[w][j][2 * op];
                ffma2(hacc[j], z2, wv);
            }
        }
#pragma unroll
        for (int j = 0; j < 8; j++) {
            float2 hp = unpack2(hacc[j]);
            float h = fmaxf(hp.x + hp.y + sbh1[lane], 0.0f);
            float part = h * swh2[lane];
#pragma unroll
            for (int off = 16; off; off >>= 1)
                part += __shfl_xor_sync(0xffffffffu, part, off);
            int row = base + j;
            if (lane == 0 && row < N) out[row] = part + sbh2v[0];
        }
        __syncwarp();
    }
}

// ---------------------------------------------------------------------------
// Launch: default stream, graph-capturable, no allocation, no sync.
// ---------------------------------------------------------------------------
extern "C" void kernel_launch(void* const* d_in, const int* in_sizes, int n_in,
                              void* d_out, int out_size)
{
    const float*     loc_x = (const float*)d_in[0];
    const float*     evt_x = (const float*)d_in[1];
    const long long* ei    = (const long long*)d_in[2];
    const float*     W_loc = (const float*)d_in[3];
    const float*     b_loc = (const float*)d_in[4];
    const float*     W_evt = (const float*)d_in[5];
    const float*     b_evt = (const float*)d_in[6];
    const float*     W_l   = (const float*)d_in[7];
    const float*     b_l   = (const float*)d_in[8];
    const float*     W_r   = (const float*)d_in[9];
    const float*     W_h1  = (const float*)d_in[10];
    const float*     b_h1  = (const float*)d_in[11];
    const float*     W_h2  = (const float*)d_in[12];
    const float*     b_h2  = (const float*)d_in[13];
    float* out = (float*)d_out;

    int NL = in_sizes[0] / 128;   // 100000
    int NE = in_sizes[1] / 128;   // 200000
    int E  = in_sizes[2] / 2;     // 1000000
    if (NL > MAX_LOC) NL = MAX_LOC;
    if (NE > MAX_EVT) NE = MAX_EVT;

    cudaFuncSetAttribute(proj_mma_kernel,
                         cudaFuncAttributeMaxDynamicSharedMemorySize, PROJ_SMEM);
    cudaFuncSetAttribute(fused_kernel,
                         cudaFuncAttributeMaxDynamicSharedMemorySize, FUSED_SMEM);

    zero_detect_kernel<<<(NL * 16 + 255) / 256, 256>>>(ei, NL * 16, NL);

    int nA = (NL + 127) / 128;            // 782 loc tiles
    int nB = (NE + 127) / 128;            // 1563 evt tiles
    proj_mma_kernel<<<nA + nB, 256, PROJ_SMEM>>>(loc_x, W_loc, b_loc, NL,
                                                 evt_x, W_evt, b_evt, NE, nA);

    int groups = (E + 3) / 4;             // 4 edges per 16-thread group
    long sc_threads = (long)groups * 16;
    int sc_blocks = (int)((sc_threads + 255) / 256);
    scatter_kernel<<<sc_blocks, 256>>>(ei, E, NL);

    fused_kernel<<<444, 256, FUSED_SMEM>>>(W_l, b_l, W_r, W_h1, b_h1, W_h2, b_h2,
                                           out, NL);
}

// round 15
// speedup vs baseline: 2.1009x; 1.0681x over previous
#include <cuda_runtime.h>
#include <cuda_bf16.h>
#include <cstdint>

typedef unsigned long long ULL;

__device__ __forceinline__ uint32_t smem_u32(const void* p) {
    uint32_t a;
    asm("{ .reg .u64 t; cvta.to.shared.u64 t, %1; cvt.u32.u64 %0, t; }"
        : "=r"(a) : "l"(p));
    return a;
}

// ---------------------------------------------------------------------------
// Scratch (device globals — no allocation allowed). 16B-aligned.
// ---------------------------------------------------------------------------
#define MAX_LOC 100000
#define MAX_EVT 200000

__device__ __align__(16) float g_evt[(size_t)MAX_EVT * 64];
__device__ __align__(16) float g_loc[(size_t)MAX_LOC * 64];
__device__ __align__(16) float g_msg[(size_t)MAX_LOC * 64];
__device__ __align__(16) float g_cnt[MAX_LOC];
__device__ int g_idx32;   // 1 if edge_index buffer is int32 (JAX x64-off)

// ---------------------------------------------------------------------------
// Zero accumulators + edge-index dtype detect (merged; one launch).
// ---------------------------------------------------------------------------
__global__ void zero_detect_kernel(const long long* __restrict__ ei,
                                   int n4 /* NL*16 */, int NL) {
    int i = blockIdx.x * blockDim.x + threadIdx.x;
    if (i < n4) ((float4*)g_msg)[i] = make_float4(0.f, 0.f, 0.f, 0.f);
    if (i < NL) g_cnt[i] = 0.0f;
    if (i == 0) {
        int is32 = 0;
#pragma unroll 8
        for (int k = 0; k < 256; k++) {
            ULL v = (ULL)ei[k];
            if (v >= 0x100000000ULL) is32 = 1;
        }
        g_idx32 = is32;
    }
}

// ---------------------------------------------------------------------------
// Shared mma.sync helpers (verified R8/R9)
// ---------------------------------------------------------------------------
__device__ __forceinline__ void ldsm_x4(uint32_t& r0, uint32_t& r1,
                                        uint32_t& r2, uint32_t& r3, uint32_t addr) {
    asm volatile("ldmatrix.sync.aligned.m8n8.x4.shared.b16 {%0,%1,%2,%3}, [%4];"
                 : "=r"(r0), "=r"(r1), "=r"(r2), "=r"(r3) : "r"(addr));
}
__device__ __forceinline__ void mma16816(float* c, const uint32_t* a,
                                         uint32_t b0, uint32_t b1) {
    asm volatile(
        "mma.sync.aligned.m16n8k16.row.col.f32.bf16.bf16.f32 "
        "{%0,%1,%2,%3}, {%4,%5,%6,%7}, {%8,%9}, {%0,%1,%2,%3};"
        : "+f"(c[0]), "+f"(c[1]), "+f"(c[2]), "+f"(c[3])
        : "r"(a[0]), "r"(a[1]), "r"(a[2]), "r"(a[3]), "r"(b0), "r"(b1));
}
__device__ __forceinline__ uint32_t bf16hi(float a, float b) {
    __nv_bfloat162 h = __float22bfloat162_rn(make_float2(a, b));
    return *(uint32_t*)&h;
}
// split a float2 into packed bf16 hi word + lo (residual) word
__device__ __forceinline__ void bf16split(float a, float b,
                                          uint32_t& hw, uint32_t& lw) {
    __nv_bfloat16 h0 = __float2bfloat16(a);
    __nv_bfloat16 h1 = __float2bfloat16(b);
    hw = (uint32_t)__bfloat16_as_ushort(h0) |
         ((uint32_t)__bfloat16_as_ushort(h1) << 16);
    lw = bf16hi(a - __bfloat162float(h0), b - __bfloat162float(h1));
}

// ---------------------------------------------------------------------------
// Tensor-core projection via mma.sync (unchanged from R9 — passing at 5e-6).
// ---------------------------------------------------------------------------
#define XH_OFF 256
#define XL_OFF (XH_OFF + 16384)
#define WH_OFF (XL_OFF + 16384)
#define WL_OFF (WH_OFF + 16384)
#define PROJ_SMEM (WL_OFF + 16384)   // 65792 B -> 3 CTAs/SM

__global__ __launch_bounds__(256, 3) void proj_mma_kernel(
    const float* __restrict__ xa, const float* __restrict__ Wa,
    const float* __restrict__ ba, int Na,
    const float* __restrict__ xb, const float* __restrict__ Wb,
    const float* __restrict__ bb, int Nb, int nA)
{
    extern __shared__ __align__(16) char sm[];
    const uint32_t sb = smem_u32(sm);
    float* sbias = (float*)sm;                 // 256 B

    const float *x, *W, *bias;
    float* out;
    int N, rowBase;
    if ((int)blockIdx.x < nA) {
        x = xa; W = Wa; bias = ba; out = g_loc; N = Na;
        rowBase = blockIdx.x * 128;
    } else {
        x = xb; W = Wb; bias = bb; out = g_evt; N = Nb;
        rowBase = (blockIdx.x - nA) * 128;
    }

    const int tid = threadIdx.x;
    const int lane = tid & 31;
    const int w = tid >> 5;

    if (tid < 64) sbias[tid] = bias[tid];

    // --- Stage W^T (full K) -> bf16 hi/lo, swizzled [n][k], 256B rows ---
    for (int i = tid; i < 64 * 64; i += 256) {
        int kp = i >> 6, n = i & 63;
        float w0 = W[(2 * kp) * 64 + n];
        float w1 = W[(2 * kp + 1) * 64 + n];
        uint32_t hw, lw;
        bf16split(w0, w1, hw, lw);
        uint32_t off = (uint32_t)n * 256 + (((kp >> 2) ^ (n & 7)) * 16) + (kp & 3) * 4;
        *(uint32_t*)(sm + WH_OFF + off) = hw;
        *(uint32_t*)(sm + WL_OFF + off) = lw;
    }

    const int warpRow = (w >> 1) * 32;
    const int warpCol = (w & 1) * 32;

    float acc[2][4][4];
#pragma unroll
    for (int mi = 0; mi < 2; mi++)
#pragma unroll
        for (int nb = 0; nb < 4; nb++)
#pragma unroll
            for (int c = 0; c < 4; c++) acc[mi][nb][c] = 0.0f;

    const int aRow = warpRow + (lane & 15);
    const int aKh  = lane >> 4;
    const int bN   = warpCol + ((lane >> 4) << 3) + (lane & 7);
    const int bKh  = (lane >> 3) & 1;

    for (int h = 0; h < 2; h++) {
        if (h) __syncthreads();

#pragma unroll
        for (int j = 0; j < 4; j++) {
            int g = tid + 256 * j;
            int r = g >> 3, u = g & 7;
            int row = rowBase + r;
            if (row >= N) row = N - 1;
            const float4* src = (const float4*)&x[(long)row * 128 + h * 64 + u * 8];
            float4 v0 = src[0];
            float4 v1 = src[1];
            uint4 hiw, low;
            bf16split(v0.x, v0.y, hiw.x, low.x);
            bf16split(v0.z, v0.w, hiw.y, low.y);
            bf16split(v1.x, v1.y, hiw.z, low.z);
            bf16split(v1.z, v1.w, hiw.w, low.w);
            uint32_t off = (uint32_t)r * 128 + ((u ^ (r & 7)) * 16);
            *(uint4*)(sm + XH_OFF + off) = hiw;
            *(uint4*)(sm + XL_OFF + off) = low;
        }
        __syncthreads();

        for (int seg = 0; seg < 3; seg++) {
            const uint32_t aBase = sb + ((seg == 2) ? XL_OFF : XH_OFF);
            const uint32_t bBase = sb + ((seg == 1) ? WL_OFF : WH_OFF);
#pragma unroll
            for (int k16l = 0; k16l < 4; k16l++) {
                const int k16g = h * 4 + k16l;
                uint32_t a[2][4], b[4][2];
#pragma unroll
                for (int mi = 0; mi < 2; mi++) {
                    int r = aRow + mi * 16;
                    uint32_t addr = aBase + (uint32_t)r * 128 +
                                    (uint32_t)(((k16l * 2 + aKh) ^ (r & 7)) * 16);
                    ldsm_x4(a[mi][0], a[mi][1], a[mi][2], a[mi][3], addr);
                }
#pragma unroll
                for (int ni2 = 0; ni2 < 2; ni2++) {
                    int n = bN + ni2 * 16;
                    uint32_t addr = bBase + (uint32_t)n * 256 +
                                    (uint32_t)(((k16g * 2 + bKh) ^ (n & 7)) * 16);
                    ldsm_x4(b[ni2 * 2][0], b[ni2 * 2][1],
                            b[ni2 * 2 + 1][0], b[ni2 * 2 + 1][1], addr);
                }
#pragma unroll
                for (int mi = 0; mi < 2; mi++)
#pragma unroll
                    for (int nb = 0; nb < 4; nb++)
                        mma16816(acc[mi][nb], a[mi], b[nb][0], b[nb][1]);
            }
        }
    }

#pragma unroll
    for (int mi = 0; mi < 2; mi++) {
#pragma unroll
        for (int part = 0; part < 2; part++) {
            int row = rowBase + warpRow + mi * 16 + (lane >> 2) + part * 8;
            if (row < N) {
                float* orow = out + (long)row * 64;
#pragma unroll
                for (int nb = 0; nb < 4; nb++) {
                    int col = warpCol + nb * 8 + (lane & 3) * 2;
                    float2 o;
                    o.x = fmaxf(acc[mi][nb][part * 2 + 0] + sbias[col], 0.0f);
                    o.y = fmaxf(acc[mi][nb][part * 2 + 1] + sbias[col + 1], 0.0f);
                    *(float2*)&orow[col] = o;
                }
            }
        }
    }
}

// ---------------------------------------------------------------------------
// Edge scatter v3: 4 edges per thread, front-batched (unchanged R9).
// ---------------------------------------------------------------------------
__global__ void scatter_kernel(const long long* __restrict__ ei, int E, int NL)
{
    long gid = (long)blockIdx.x * blockDim.x + threadIdx.x;
    int g4 = (int)(gid >> 4);
    int q  = (int)(gid & 15);
    int e0 = g4 * 4;
    if (e0 >= E) return;
    const int idx32 = g_idx32;
    const int ne = (E - e0 < 4) ? (E - e0) : 4;

    int s[4], d[4];
#pragma unroll
    for (int j = 0; j < 4; j++) {
        int e = e0 + ((j < ne) ? j : 0);
        if (idx32) {
            const int* e32 = (const int*)ei;
            s[j] = e32[e];
            d[j] = e32[E + e];
        } else {
            s[j] = (int)ei[e];
            d[j] = (int)ei[(long)E + e];
        }
    }

    bool ok[4];
    float4 v[4];
#pragma unroll
    for (int j = 0; j < 4; j++) {
        ok[j] = (j < ne) && (unsigned)s[j] < (unsigned)MAX_EVT &&
                (unsigned)d[j] < (unsigned)NL;
        v[j] = ok[j] ? *(const float4*)&g_evt[(long)s[j] * 64 + q * 4]
                     : make_float4(0.f, 0.f, 0.f, 0.f);
    }
#pragma unroll
    for (int j = 0; j < 4; j++) {
        if (ok[j]) {
            atomicAdd((float4*)&g_msg[(long)d[j] * 64 + q * 4], v[j]);
            if (q == 0) atomicAdd(&g_cnt[d[j]], 1.0f);
        }
    }
}

// ---------------------------------------------------------------------------
// Fused SAGE + head via mma.sync:
//   z = relu([agg | loc] @ [Wl ; Wr] + bl)     (K=128 GEMM, proj structure;
//     h=0 half staged from g_msg * 1/max(cnt,1), h=1 half from g_loc)
//   h = relu(z @ Wh1 + bh1); logit = h @ Wh2 + bh2
// z is re-split to bf16 hi/lo into the freed X buffers; head is an
// m16 x n32 x k64 mma chain per warp + 4-lane shuffle reduction.
// ---------------------------------------------------------------------------
#define F_BL   0
#define F_BH1  256
#define F_WH2  384
#define F_BH2  512
#define F_XH   768
#define F_XL   (F_XH + 16384)
#define F_WH   (F_XL + 16384)
#define F_WL   (F_WH + 16384)
#define F_H1H  (F_WL + 16384)
#define F_H1L  (F_H1H + 4096)
#define FUSEDM_SMEM (F_H1L + 4096)   // 74496 B -> 3 CTAs/SM

__global__ __launch_bounds__(256, 3) void fused_mma_kernel(
    const float* __restrict__ Wl, const float* __restrict__ bl,
    const float* __restrict__ Wr,
    const float* __restrict__ Wh1, const float* __restrict__ bh1,
    const float* __restrict__ Wh2, const float* __restrict__ bh2,
    float* __restrict__ out, int N)
{
    extern __shared__ __align__(16) char sm[];
    const uint32_t sb = smem_u32(sm);
    float* sbl  = (float*)(sm + F_BL);
    float* sbh1 = (float*)(sm + F_BH1);
    float* swh2 = (float*)(sm + F_WH2);
    float* sbh2 = (float*)(sm + F_BH2);

    const int tid = threadIdx.x;
    const int lane = tid & 31;
    const int w = tid >> 5;
    const int rowBase = blockIdx.x * 128;

    if (tid < 64) sbl[tid] = bl[tid];
    if (tid < 32) { sbh1[tid] = bh1[tid]; swh2[tid] = Wh2[tid]; }
    if (tid == 0) sbh2[0] = bh2[0];

    // --- Stage stacked W = [Wl ; Wr]^T -> bf16 hi/lo, [n][k] 256B rows ---
    for (int i = tid; i < 64 * 64; i += 256) {
        int kp = i >> 6, n = i & 63;
        int k0 = 2 * kp;
        float w0 = (k0 < 64) ? Wl[k0 * 64 + n] : Wr[(k0 - 64) * 64 + n];
        float w1 = (k0 < 64) ? Wl[(k0 + 1) * 64 + n] : Wr[(k0 - 63) * 64 + n];
        uint32_t hw, lw;
        bf16split(w0, w1, hw, lw);
        uint32_t off = (uint32_t)n * 256 + (((kp >> 2) ^ (n & 7)) * 16) + (kp & 3) * 4;
        *(uint32_t*)(sm + F_WH + off) = hw;
        *(uint32_t*)(sm + F_WL + off) = lw;
    }
    // --- Stage Wh1^T -> bf16 hi/lo, [n 0..31][k 0..63] 128B rows ---
    for (int i = tid; i < 32 * 32; i += 256) {
        int kp = i >> 5, n = i & 31;
        float w0 = Wh1[(2 * kp) * 32 + n];
        float w1 = Wh1[(2 * kp + 1) * 32 + n];
        uint32_t hw, lw;
        bf16split(w0, w1, hw, lw);
        uint32_t off = (uint32_t)n * 128 + (((kp >> 2) ^ (n & 7)) * 16) + (kp & 3) * 4;
        *(uint32_t*)(sm + F_H1H + off) = hw;
        *(uint32_t*)(sm + F_H1L + off) = lw;
    }

    const int warpRow = (w >> 1) * 32;
    const int warpCol = (w & 1) * 32;

    float acc[2][4][4];
#pragma unroll
    for (int mi = 0; mi < 2; mi++)
#pragma unroll
        for (int nb = 0; nb < 4; nb++)
#pragma unroll
            for (int c = 0; c < 4; c++) acc[mi][nb][c] = 0.0f;

    const int aRow = warpRow + (lane & 15);
    const int aKh  = lane >> 4;
    const int bN   = warpCol + ((lane >> 4) << 3) + (lane & 7);
    const int bKh  = (lane >> 3) & 1;

    // ===== z-GEMM: K=128 in two halves (agg, then loc) =====
    for (int h = 0; h < 2; h++) {
        if (h) __syncthreads();

        // Stage A half: h=0 agg = msg * inv(cnt); h=1 loc
#pragma unroll
        for (int j = 0; j < 4; j++) {
            int g = tid + 256 * j;
            int r = g >> 3, u = g & 7;
            int row = rowBase + r;
            if (row >= N) row = N - 1;
            float4 v0, v1;
            if (h == 0) {
                float inv = 1.0f / fmaxf(g_cnt[row], 1.0f);
                const float4* src = (const float4*)&g_msg[(long)row * 64 + u * 8];
                v0 = src[0]; v1 = src[1];
                v0.x *= inv; v0.y *= inv; v0.z *= inv; v0.w *= inv;
                v1.x *= inv; v1.y *= inv; v1.z *= inv; v1.w *= inv;
            } else {
                const float4* src = (const float4*)&g_loc[(long)row * 64 + u * 8];
                v0 = src[0]; v1 = src[1];
            }
            uint4 hiw, low;
            bf16split(v0.x, v0.y, hiw.x, low.x);
            bf16split(v0.z, v0.w, hiw.y, low.y);
            bf16split(v1.x, v1.y, hiw.z, low.z);
            bf16split(v1.z, v1.w, hiw.w, low.w);
            uint32_t off = (uint32_t)r * 128 + ((u ^ (r & 7)) * 16);
            *(uint4*)(sm + F_XH + off) = hiw;
            *(uint4*)(sm + F_XL + off) = low;
        }
        __syncthreads();

        for (int seg = 0; seg < 3; seg++) {
            const uint32_t aBase = sb + ((seg == 2) ? F_XL : F_XH);
            const uint32_t bBase = sb + ((seg == 1) ? F_WL : F_WH);
#pragma unroll
            for (int k16l = 0; k16l < 4; k16l++) {
                const int k16g = h * 4 + k16l;
                uint32_t a[2][4], b[4][2];
#pragma unroll
                for (int mi = 0; mi < 2; mi++) {
                    int r = aRow + mi * 16;
                    uint32_t addr = aBase + (uint32_t)r * 128 +
                                    (uint32_t)(((k16l * 2 + aKh) ^ (r & 7)) * 16);
                    ldsm_x4(a[mi][0], a[mi][1], a[mi][2], a[mi][3], addr);
                }
#pragma unroll
                for (int ni2 = 0; ni2 < 2; ni2++) {
                    int n = bN + ni2 * 16;
                    uint32_t addr = bBase + (uint32_t)n * 256 +
                                    (uint32_t)(((k16g * 2 + bKh) ^ (n & 7)) * 16);
                    ldsm_x4(b[ni2 * 2][0], b[ni2 * 2][1],
                            b[ni2 * 2 + 1][0], b[ni2 * 2 + 1][1], addr);
                }
#pragma unroll
                for (int mi = 0; mi < 2; mi++)
#pragma unroll
                    for (int nb = 0; nb < 4; nb++)
                        mma16816(acc[mi][nb], a[mi], b[nb][0], b[nb][1]);
            }
        }
    }

    // ===== z = relu(acc + bl) -> bf16 hi/lo into freed X buffers =====
    __syncthreads();   // all warps done reading X before overwrite
#pragma unroll
    for (int mi = 0; mi < 2; mi++) {
#pragma unroll
        for (int part = 0; part < 2; part++) {
            int r = warpRow + mi * 16 + (lane >> 2) + part * 8;   // local 0..127
#pragma unroll
            for (int nb = 0; nb < 4; nb++) {
                int col = warpCol + nb * 8 + (lane & 3) * 2;
                float z0 = fmaxf(acc[mi][nb][part * 2 + 0] + sbl[col], 0.0f);
                float z1 = fmaxf(acc[mi][nb][part * 2 + 1] + sbl[col + 1], 0.0f);
                uint32_t hw, lw;
                bf16split(z0, z1, hw, lw);
                uint32_t off = (uint32_t)r * 128 +
                               (((col >> 3) ^ (r & 7)) * 16) + (col & 7) * 2;
                *(uint32_t*)(sm + F_XH + off) = hw;
                *(uint32_t*)(sm + F_XL + off) = lw;
            }
        }
    }
    __syncthreads();

    // ===== head: h[16,32] = relu(z @ Wh1 + bh1) per warp, then logit =====
    const int aRowH = w * 16 + (lane & 15);
    const int bNh   = ((lane >> 4) << 3) + (lane & 7);

    float hacc[4][4];
#pragma unroll
    for (int nb = 0; nb < 4; nb++)
#pragma unroll
        for (int c = 0; c < 4; c++) hacc[nb][c] = 0.0f;

    for (int seg = 0; seg < 3; seg++) {
        const uint32_t aBase = sb + ((seg == 2) ? F_XL : F_XH);
        const uint32_t bBase = sb + ((seg == 1) ? F_H1L : F_H1H);
#pragma unroll
        for (int k16 = 0; k16 < 4; k16++) {
            uint32_t a[4], b[4][2];
            {
                int r = aRowH;
                uint32_t addr = aBase + (uint32_t)r * 128 +
                                (uint32_t)(((k16 * 2 + aKh) ^ (r & 7)) * 16);
                ldsm_x4(a[0], a[1], a[2], a[3], addr);
            }
#pragma unroll
            for (int ni2 = 0; ni2 < 2; ni2++) {
                int n = bNh + ni2 * 16;
                uint32_t addr = bBase + (uint32_t)n * 128 +
                                (uint32_t)(((k16 * 2 + bKh) ^ (n & 7)) * 16);
                ldsm_x4(b[ni2 * 2][0], b[ni2 * 2][1],
                        b[ni2 * 2 + 1][0], b[ni2 * 2 + 1][1], addr);
            }
#pragma unroll
            for (int nb = 0; nb < 4; nb++)
                mma16816(hacc[nb], a, b[nb][0], b[nb][1]);
        }
    }

#pragma unroll
    for (int part = 0; part < 2; part++) {
        float partial = 0.0f;
#pragma unroll
        for (int nb = 0; nb < 4; nb++) {
#pragma unroll
            for (int i = 0; i < 2; i++) {
                int col = nb * 8 + (lane & 3) * 2 + i;
                float hv = fmaxf(hacc[nb][part * 2 + i] + sbh1[col], 0.0f);
                partial += hv * swh2[col];
            }
        }
        partial += __shfl_xor_sync(0xffffffffu, partial, 1);
        partial += __shfl_xor_sync(0xffffffffu, partial, 2);
        int row = rowBase + w * 16 + (lane >> 2) + part * 8;
        if ((lane & 3) == 0 && row < N) out[row] = partial + sbh2[0];
    }
}

// ---------------------------------------------------------------------------
// Launch: default stream, graph-capturable, no allocation, no sync.
// ---------------------------------------------------------------------------
extern "C" void kernel_launch(void* const* d_in, const int* in_sizes, int n_in,
                              void* d_out, int out_size)
{
    const float*     loc_x = (const float*)d_in[0];
    const float*     evt_x = (const float*)d_in[1];
    const long long* ei    = (const long long*)d_in[2];
    const float*     W_loc = (const float*)d_in[3];
    const float*     b_loc = (const float*)d_in[4];
    const float*     W_evt = (const float*)d_in[5];
    const float*     b_evt = (const float*)d_in[6];
    const float*     W_l   = (const float*)d_in[7];
    const float*     b_l   = (const float*)d_in[8];
    const float*     W_r   = (const float*)d_in[9];
    const float*     W_h1  = (const float*)d_in[10];
    const float*     b_h1  = (const float*)d_in[11];
    const float*     W_h2  = (const float*)d_in[12];
    const float*     b_h2  = (const float*)d_in[13];
    float* out = (float*)d_out;

    int NL = in_sizes[0] / 128;   // 100000
    int NE = in_sizes[1] / 128;   // 200000
    int E  = in_sizes[2] / 2;     // 1000000
    if (NL > MAX_LOC) NL = MAX_LOC;
    if (NE > MAX_EVT) NE = MAX_EVT;

    cudaFuncSetAttribute(proj_mma_kernel,
                         cudaFuncAttributeMaxDynamicSharedMemorySize, PROJ_SMEM);
    cudaFuncSetAttribute(fused_mma_kernel,
                         cudaFuncAttributeMaxDynamicSharedMemorySize, FUSEDM_SMEM);

    zero_detect_kernel<<<(NL * 16 + 255) / 256, 256>>>(ei, NL * 16, NL);

    int nA = (NL + 127) / 128;            // 782 loc tiles
    int nB = (NE + 127) / 128;            // 1563 evt tiles
    proj_mma_kernel<<<nA + nB, 256, PROJ_SMEM>>>(loc_x, W_loc, b_loc, NL,
                                                 evt_x, W_evt, b_evt, NE, nA);

    int groups = (E + 3) / 4;             // 4 edges per 16-thread group
    long sc_threads = (long)groups * 16;
    int sc_blocks = (int)((sc_threads + 255) / 256);
    scatter_kernel<<<sc_blocks, 256>>>(ei, E, NL);

    fused_mma_kernel<<<nA, 256, FUSEDM_SMEM>>>(W_l, b_l, W_r, W_h1, b_h1,
                                               W_h2, b_h2, out, NL);
}

// round 16
// speedup vs baseline: 2.4478x; 1.1651x over previous
#include <cuda_runtime.h>
#include <cuda_bf16.h>
#include <cstdint>

typedef unsigned long long ULL;

__device__ __forceinline__ uint32_t smem_u32(const void* p) {
    uint32_t a;
    asm("{ .reg .u64 t; cvta.to.shared.u64 t, %1; cvt.u32.u64 %0, t; }"
        : "=r"(a) : "l"(p));
    return a;
}

// ---------------------------------------------------------------------------
// Scratch (device globals — no allocation allowed). 16B-aligned.
// ---------------------------------------------------------------------------
#define MAX_LOC 100000
#define MAX_EVT 200000

__device__ __align__(16) float g_evt[(size_t)MAX_EVT * 64];
__device__ __align__(16) float g_loc[(size_t)MAX_LOC * 64];
__device__ __align__(16) float g_msg[(size_t)MAX_LOC * 64];
__device__ __align__(16) float g_cnt[MAX_LOC];
__device__ int g_idx32;

// Pre-split weight images (bf16 hi/lo, already in swizzled smem layout):
__device__ __align__(16) uint32_t g_wp[2][2][4096];  // [which][hi/lo] proj W^T
__device__ __align__(16) uint32_t g_ws[2][4096];     // [hi/lo] stacked [Wl;Wr]^T
__device__ __align__(16) uint32_t g_wh[2][1024];     // [hi/lo] Wh1^T

// ---------------------------------------------------------------------------
// bf16 hi/lo split, 6 instrs/pair: one F2FP.PACK for hi, rebuild hi floats
// via shift/mask, subtract, one F2FP.PACK for lo. Bit-identical to the
// previous per-element version.
// ---------------------------------------------------------------------------
__device__ __forceinline__ void bf16split(float a, float b,
                                          uint32_t& hw, uint32_t& lw) {
    __nv_bfloat162 h = __float22bfloat162_rn(make_float2(a, b));
    hw = *(uint32_t*)&h;
    float ah = __uint_as_float(hw << 16);
    float bh = __uint_as_float(hw & 0xFFFF0000u);
    __nv_bfloat162 l = __float22bfloat162_rn(make_float2(a - ah, b - bh));
    lw = *(uint32_t*)&l;
}

// ---------------------------------------------------------------------------
// Prep launch: zero accumulators + dtype detect + pre-split all weights into
// their swizzled smem images. Deterministic every launch (graph replays).
// Blocks [0, zb) do the zeroing; blocks [zb, zb+52) do weights.
// ---------------------------------------------------------------------------
__global__ void prep_kernel(const long long* __restrict__ ei,
                            const float* __restrict__ Wloc,
                            const float* __restrict__ Wevt,
                            const float* __restrict__ Wl,
                            const float* __restrict__ Wr,
                            const float* __restrict__ Wh1,
                            int n4 /* NL*16 */, int NL, int zb)
{
    if ((int)blockIdx.x < zb) {
        int i = blockIdx.x * 256 + threadIdx.x;
        if (i < n4) ((float4*)g_msg)[i] = make_float4(0.f, 0.f, 0.f, 0.f);
        if (i < NL) g_cnt[i] = 0.0f;
        if (i == 0) {
            int is32 = 0;
#pragma unroll 8
            for (int k = 0; k < 256; k++) {
                ULL v = (ULL)ei[k];
                if (v >= 0x100000000ULL) is32 = 1;
            }
            g_idx32 = is32;
        }
        return;
    }

    int j = ((int)blockIdx.x - zb) * 256 + threadIdx.x;
    if (j < 8192) {                       // proj weights: 2 matrices
        int which = j >> 12, p = j & 4095;
        int kp = p >> 6, n = p & 63;
        const float* W = which ? Wevt : Wloc;
        float w0 = W[(2 * kp) * 64 + n];
        float w1 = W[(2 * kp + 1) * 64 + n];
        uint32_t hw, lw;
        bf16split(w0, w1, hw, lw);
        uint32_t word = (uint32_t)n * 64 + (((kp >> 2) ^ (n & 7)) * 4) + (kp & 3);
        g_wp[which][0][word] = hw;
        g_wp[which][1][word] = lw;
    } else if (j < 12288) {               // stacked [Wl ; Wr]^T
        int p = j - 8192;
        int kp = p >> 6, n = p & 63;
        int k0 = 2 * kp;
        float w0 = (k0 < 64) ? Wl[k0 * 64 + n] : Wr[(k0 - 64) * 64 + n];
        float w1 = (k0 < 64) ? Wl[(k0 + 1) * 64 + n] : Wr[(k0 - 63) * 64 + n];
        uint32_t hw, lw;
        bf16split(w0, w1, hw, lw);
        uint32_t word = (uint32_t)n * 64 + (((kp >> 2) ^ (n & 7)) * 4) + (kp & 3);
        g_ws[0][word] = hw;
        g_ws[1][word] = lw;
    } else if (j < 13312) {               // Wh1^T
        int p = j - 12288;
        int kp = p >> 5, n = p & 31;
        float w0 = Wh1[(2 * kp) * 32 + n];
        float w1 = Wh1[(2 * kp + 1) * 32 + n];
        uint32_t hw, lw;
        bf16split(w0, w1, hw, lw);
        uint32_t word = (uint32_t)n * 32 + (((kp >> 2) ^ (n & 7)) * 4) + (kp & 3);
        g_wh[0][word] = hw;
        g_wh[1][word] = lw;
    }
}

// ---------------------------------------------------------------------------
// mma.sync helpers (verified R8+)
// ---------------------------------------------------------------------------
__device__ __forceinline__ void ldsm_x4(uint32_t& r0, uint32_t& r1,
                                        uint32_t& r2, uint32_t& r3, uint32_t addr) {
    asm volatile("ldmatrix.sync.aligned.m8n8.x4.shared.b16 {%0,%1,%2,%3}, [%4];"
                 : "=r"(r0), "=r"(r1), "=r"(r2), "=r"(r3) : "r"(addr));
}
__device__ __forceinline__ void mma16816(float* c, const uint32_t* a,
                                         uint32_t b0, uint32_t b1) {
    asm volatile(
        "mma.sync.aligned.m16n8k16.row.col.f32.bf16.bf16.f32 "
        "{%0,%1,%2,%3}, {%4,%5,%6,%7}, {%8,%9}, {%0,%1,%2,%3};"
        : "+f"(c[0]), "+f"(c[1]), "+f"(c[2]), "+f"(c[3])
        : "r"(a[0]), "r"(a[1]), "r"(a[2]), "r"(a[3]), "r"(b0), "r"(b1));
}

// ---------------------------------------------------------------------------
// Tensor-core projection via mma.sync. Weight staging is now a plain uint4
// copy of the pre-split image; X staging uses the 6-instr bf16split.
// ---------------------------------------------------------------------------
#define XH_OFF 256
#define XL_OFF (XH_OFF + 16384)
#define WH_OFF (XL_OFF + 16384)
#define WL_OFF (WH_OFF + 16384)
#define PROJ_SMEM (WL_OFF + 16384)   // 65792 B -> 3 CTAs/SM

__global__ __launch_bounds__(256, 3) void proj_mma_kernel(
    const float* __restrict__ xa, const float* __restrict__ ba, int Na,
    const float* __restrict__ xb, const float* __restrict__ bb, int Nb, int nA)
{
    extern __shared__ __align__(16) char sm[];
    const uint32_t sb = smem_u32(sm);
    float* sbias = (float*)sm;                 // 256 B

    const float *x, *bias;
    float* out;
    int N, rowBase, which;
    if ((int)blockIdx.x < nA) {
        x = xa; bias = ba; out = g_loc; N = Na; which = 0;
        rowBase = blockIdx.x * 128;
    } else {
        x = xb; bias = bb; out = g_evt; N = Nb; which = 1;
        rowBase = (blockIdx.x - nA) * 128;
    }

    const int tid = threadIdx.x;
    const int lane = tid & 31;
    const int w = tid >> 5;

    if (tid < 64) sbias[tid] = bias[tid];

    // --- Stage W image: straight 16B copies ---
    {
        const uint4* srcH = (const uint4*)g_wp[which][0];
        const uint4* srcL = (const uint4*)g_wp[which][1];
        uint4* dstH = (uint4*)(sm + WH_OFF);
        uint4* dstL = (uint4*)(sm + WL_OFF);
#pragma unroll
        for (int i = 0; i < 4; i++) {
            dstH[tid + 256 * i] = srcH[tid + 256 * i];
            dstL[tid + 256 * i] = srcL[tid + 256 * i];
        }
    }

    const int warpRow = (w >> 1) * 32;
    const int warpCol = (w & 1) * 32;

    float acc[2][4][4];
#pragma unroll
    for (int mi = 0; mi < 2; mi++)
#pragma unroll
        for (int nb = 0; nb < 4; nb++)
#pragma unroll
            for (int c = 0; c < 4; c++) acc[mi][nb][c] = 0.0f;

    const int aRow = warpRow + (lane & 15);
    const int aKh  = lane >> 4;
    const int bN   = warpCol + ((lane >> 4) << 3) + (lane & 7);
    const int bKh  = (lane >> 3) & 1;

    for (int h = 0; h < 2; h++) {
        if (h) __syncthreads();

#pragma unroll
        for (int j = 0; j < 4; j++) {
            int g = tid + 256 * j;
            int r = g >> 3, u = g & 7;
            int row = rowBase + r;
            if (row >= N) row = N - 1;
            const float4* src = (const float4*)&x[(long)row * 128 + h * 64 + u * 8];
            float4 v0 = src[0];
            float4 v1 = src[1];
            uint4 hiw, low;
            bf16split(v0.x, v0.y, hiw.x, low.x);
            bf16split(v0.z, v0.w, hiw.y, low.y);
            bf16split(v1.x, v1.y, hiw.z, low.z);
            bf16split(v1.z, v1.w, hiw.w, low.w);
            uint32_t off = (uint32_t)r * 128 + ((u ^ (r & 7)) * 16);
            *(uint4*)(sm + XH_OFF + off) = hiw;
            *(uint4*)(sm + XL_OFF + off) = low;
        }
        __syncthreads();

        for (int seg = 0; seg < 3; seg++) {
            const uint32_t aBase = sb + ((seg == 2) ? XL_OFF : XH_OFF);
            const uint32_t bBase = sb + ((seg == 1) ? WL_OFF : WH_OFF);
#pragma unroll
            for (int k16l = 0; k16l < 4; k16l++) {
                const int k16g = h * 4 + k16l;
                uint32_t a[2][4], b[4][2];
#pragma unroll
                for (int mi = 0; mi < 2; mi++) {
                    int r = aRow + mi * 16;
                    uint32_t addr = aBase + (uint32_t)r * 128 +
                                    (uint32_t)(((k16l * 2 + aKh) ^ (r & 7)) * 16);
                    ldsm_x4(a[mi][0], a[mi][1], a[mi][2], a[mi][3], addr);
                }
#pragma unroll
                for (int ni2 = 0; ni2 < 2; ni2++) {
                    int n = bN + ni2 * 16;
                    uint32_t addr = bBase + (uint32_t)n * 256 +
                                    (uint32_t)(((k16g * 2 + bKh) ^ (n & 7)) * 16);
                    ldsm_x4(b[ni2 * 2][0], b[ni2 * 2][1],
                            b[ni2 * 2 + 1][0], b[ni2 * 2 + 1][1], addr);
                }
#pragma unroll
                for (int mi = 0; mi < 2; mi++)
#pragma unroll
                    for (int nb = 0; nb < 4; nb++)
                        mma16816(acc[mi][nb], a[mi], b[nb][0], b[nb][1]);
            }
        }
    }

#pragma unroll
    for (int mi = 0; mi < 2; mi++) {
#pragma unroll
        for (int part = 0; part < 2; part++) {
            int row = rowBase + warpRow + mi * 16 + (lane >> 2) + part * 8;
            if (row < N) {
                float* orow = out + (long)row * 64;
#pragma unroll
                for (int nb = 0; nb < 4; nb++) {
                    int col = warpCol + nb * 8 + (lane & 3) * 2;
                    float2 o;
                    o.x = fmaxf(acc[mi][nb][part * 2 + 0] + sbias[col], 0.0f);
                    o.y = fmaxf(acc[mi][nb][part * 2 + 1] + sbias[col + 1], 0.0f);
                    *(float2*)&orow[col] = o;
                }
            }
        }
    }
}

// ---------------------------------------------------------------------------
// Edge scatter: 4 edges per thread, front-batched (unchanged R9 — MLP and
// occupancy trade-off is at its latency-BW-product optimum).
// ---------------------------------------------------------------------------
__global__ void scatter_kernel(const long long* __restrict__ ei, int E, int NL)
{
    long gid = (long)blockIdx.x * blockDim.x + threadIdx.x;
    int g4 = (int)(gid >> 4);
    int q  = (int)(gid & 15);
    int e0 = g4 * 4;
    if (e0 >= E) return;
    const int idx32 = g_idx32;
    const int ne = (E - e0 < 4) ? (E - e0) : 4;

    int s[4], d[4];
#pragma unroll
    for (int j = 0; j < 4; j++) {
        int e = e0 + ((j < ne) ? j : 0);
        if (idx32) {
            const int* e32 = (const int*)ei;
            s[j] = e32[e];
            d[j] = e32[E + e];
        } else {
            s[j] = (int)ei[e];
            d[j] = (int)ei[(long)E + e];
        }
    }

    bool ok[4];
    float4 v[4];
#pragma unroll
    for (int j = 0; j < 4; j++) {
        ok[j] = (j < ne) && (unsigned)s[j] < (unsigned)MAX_EVT &&
                (unsigned)d[j] < (unsigned)NL;
        v[j] = ok[j] ? *(const float4*)&g_evt[(long)s[j] * 64 + q * 4]
                     : make_float4(0.f, 0.f, 0.f, 0.f);
    }
#pragma unroll
    for (int j = 0; j < 4; j++) {
        if (ok[j]) {
            atomicAdd((float4*)&g_msg[(long)d[j] * 64 + q * 4], v[j]);
            if (q == 0) atomicAdd(&g_cnt[d[j]], 1.0f);
        }
    }
}

// ---------------------------------------------------------------------------
// Fused SAGE + head via mma.sync (R15 structure; weight staging now copies
// the pre-split images, staging uses fast bf16split).
// ---------------------------------------------------------------------------
#define F_BL   0
#define F_BH1  256
#define F_WH2  384
#define F_BH2  512
#define F_XH   768
#define F_XL   (F_XH + 16384)
#define F_WH   (F_XL + 16384)
#define F_WL   (F_WH + 16384)
#define F_H1H  (F_WL + 16384)
#define F_H1L  (F_H1H + 4096)
#define FUSEDM_SMEM (F_H1L + 4096)   // 74496 B -> 3 CTAs/SM

__global__ __launch_bounds__(256, 3) void fused_mma_kernel(
    const float* __restrict__ bl, const float* __restrict__ bh1,
    const float* __restrict__ Wh2, const float* __restrict__ bh2,
    float* __restrict__ out, int N)
{
    extern __shared__ __align__(16) char sm[];
    const uint32_t sb = smem_u32(sm);
    float* sbl  = (float*)(sm + F_BL);
    float* sbh1 = (float*)(sm + F_BH1);
    float* swh2 = (float*)(sm + F_WH2);
    float* sbh2 = (float*)(sm + F_BH2);

    const int tid = threadIdx.x;
    const int lane = tid & 31;
    const int w = tid >> 5;
    const int rowBase = blockIdx.x * 128;

    if (tid < 64) sbl[tid] = bl[tid];
    if (tid < 32) { sbh1[tid] = bh1[tid]; swh2[tid] = Wh2[tid]; }
    if (tid == 0) sbh2[0] = bh2[0];

    // --- Stage weight images: straight 16B copies ---
    {
        const uint4* sH = (const uint4*)g_ws[0];
        const uint4* sL = (const uint4*)g_ws[1];
        uint4* dH = (uint4*)(sm + F_WH);
        uint4* dL = (uint4*)(sm + F_WL);
#pragma unroll
        for (int i = 0; i < 4; i++) {
            dH[tid + 256 * i] = sH[tid + 256 * i];
            dL[tid + 256 * i] = sL[tid + 256 * i];
        }
        ((uint4*)(sm + F_H1H))[tid] = ((const uint4*)g_wh[0])[tid];
        ((uint4*)(sm + F_H1L))[tid] = ((const uint4*)g_wh[1])[tid];
    }

    const int warpRow = (w >> 1) * 32;
    const int warpCol = (w & 1) * 32;

    float acc[2][4][4];
#pragma unroll
    for (int mi = 0; mi < 2; mi++)
#pragma unroll
        for (int nb = 0; nb < 4; nb++)
#pragma unroll
            for (int c = 0; c < 4; c++) acc[mi][nb][c] = 0.0f;

    const int aRow = warpRow + (lane & 15);
    const int aKh  = lane >> 4;
    const int bN   = warpCol + ((lane >> 4) << 3) + (lane & 7);
    const int bKh  = (lane >> 3) & 1;

    // ===== z-GEMM: K=128 in two halves (agg, then loc) =====
    for (int h = 0; h < 2; h++) {
        if (h) __syncthreads();

#pragma unroll
        for (int j = 0; j < 4; j++) {
            int g = tid + 256 * j;
            int r = g >> 3, u = g & 7;
            int row = rowBase + r;
            if (row >= N) row = N - 1;
            float4 v0, v1;
            if (h == 0) {
                float inv = 1.0f / fmaxf(g_cnt[row], 1.0f);
                const float4* src = (const float4*)&g_msg[(long)row * 64 + u * 8];
                v0 = src[0]; v1 = src[1];
                v0.x *= inv; v0.y *= inv; v0.z *= inv; v0.w *= inv;
                v1.x *= inv; v1.y *= inv; v1.z *= inv; v1.w *= inv;
            } else {
                const float4* src = (const float4*)&g_loc[(long)row * 64 + u * 8];
                v0 = src[0]; v1 = src[1];
            }
            uint4 hiw, low;
            bf16split(v0.x, v0.y, hiw.x, low.x);
            bf16split(v0.z, v0.w, hiw.y, low.y);
            bf16split(v1.x, v1.y, hiw.z, low.z);
            bf16split(v1.z, v1.w, hiw.w, low.w);
            uint32_t off = (uint32_t)r * 128 + ((u ^ (r & 7)) * 16);
            *(uint4*)(sm + F_XH + off) = hiw;
            *(uint4*)(sm + F_XL + off) = low;
        }
        __syncthreads();

        for (int seg = 0; seg < 3; seg++) {
            const uint32_t aBase = sb + ((seg == 2) ? F_XL : F_XH);
            const uint32_t bBase = sb + ((seg == 1) ? F_WL : F_WH);
#pragma unroll
            for (int k16l = 0; k16l < 4; k16l++) {
                const int k16g = h * 4 + k16l;
                uint32_t a[2][4], b[4][2];
#pragma unroll
                for (int mi = 0; mi < 2; mi++) {
                    int r = aRow + mi * 16;
                    uint32_t addr = aBase + (uint32_t)r * 128 +
                                    (uint32_t)(((k16l * 2 + aKh) ^ (r & 7)) * 16);
                    ldsm_x4(a[mi][0], a[mi][1], a[mi][2], a[mi][3], addr);
                }
#pragma unroll
                for (int ni2 = 0; ni2 < 2; ni2++) {
                    int n = bN + ni2 * 16;
                    uint32_t addr = bBase + (uint32_t)n * 256 +
                                    (uint32_t)(((k16g * 2 + bKh) ^ (n & 7)) * 16);
                    ldsm_x4(b[ni2 * 2][0], b[ni2 * 2][1],
                            b[ni2 * 2 + 1][0], b[ni2 * 2 + 1][1], addr);
                }
#pragma unroll
                for (int mi = 0; mi < 2; mi++)
#pragma unroll
                    for (int nb = 0; nb < 4; nb++)
                        mma16816(acc[mi][nb], a[mi], b[nb][0], b[nb][1]);
            }
        }
    }

    // ===== z = relu(acc + bl) -> bf16 hi/lo into freed X buffers =====
    __syncthreads();
#pragma unroll
    for (int mi = 0; mi < 2; mi++) {
#pragma unroll
        for (int part = 0; part < 2; part++) {
            int r = warpRow + mi * 16 + (lane >> 2) + part * 8;
#pragma unroll
            for (int nb = 0; nb < 4; nb++) {
                int col = warpCol + nb * 8 + (lane & 3) * 2;
                float z0 = fmaxf(acc[mi][nb][part * 2 + 0] + sbl[col], 0.0f);
                float z1 = fmaxf(acc[mi][nb][part * 2 + 1] + sbl[col + 1], 0.0f);
                uint32_t hw, lw;
                bf16split(z0, z1, hw, lw);
                uint32_t off = (uint32_t)r * 128 +
                               (((col >> 3) ^ (r & 7)) * 16) + (col & 7) * 2;
                *(uint32_t*)(sm + F_XH + off) = hw;
                *(uint32_t*)(sm + F_XL + off) = lw;
            }
        }
    }
    __syncthreads();

    // ===== head: h[16,32] = relu(z @ Wh1 + bh1) per warp, then logit =====
    const int aRowH = w * 16 + (lane & 15);
    const int bNh   = ((lane >> 4) << 3) + (lane & 7);

    float hacc[4][4];
#pragma unroll
    for (int nb = 0; nb < 4; nb++)
#pragma unroll
        for (int c = 0; c < 4; c++) hacc[nb][c] = 0.0f;

    for (int seg = 0; seg < 3; seg++) {
        const uint32_t aBase = sb + ((seg == 2) ? F_XL : F_XH);
        const uint32_t bBase = sb + ((seg == 1) ? F_H1L : F_H1H);
#pragma unroll
        for (int k16 = 0; k16 < 4; k16++) {
            uint32_t a[4], b[4][2];
            {
                int r = aRowH;
                uint32_t addr = aBase + (uint32_t)r * 128 +
                                (uint32_t)(((k16 * 2 + aKh) ^ (r & 7)) * 16);
                ldsm_x4(a[0], a[1], a[2], a[3], addr);
            }
#pragma unroll
            for (int ni2 = 0; ni2 < 2; ni2++) {
                int n = bNh + ni2 * 16;
                uint32_t addr = bBase + (uint32_t)n * 128 +
                                (uint32_t)(((k16 * 2 + bKh) ^ (n & 7)) * 16);
                ldsm_x4(b[ni2 * 2][0], b[ni2 * 2][1],
                        b[ni2 * 2 + 1][0], b[ni2 * 2 + 1][1], addr);
            }
#pragma unroll
            for (int nb = 0; nb < 4; nb++)
                mma16816(hacc[nb], a, b[nb][0], b[nb][1]);
        }
    }

#pragma unroll
    for (int part = 0; part < 2; part++) {
        float partial = 0.0f;
#pragma unroll
        for (int nb = 0; nb < 4; nb++) {
#pragma unroll
            for (int i = 0; i < 2; i++) {
                int col = nb * 8 + (lane & 3) * 2 + i;
                float hv = fmaxf(hacc[nb][part * 2 + i] + sbh1[col], 0.0f);
                partial += hv * swh2[col];
            }
        }
        partial += __shfl_xor_sync(0xffffffffu, partial, 1);
        partial += __shfl_xor_sync(0xffffffffu, partial, 2);
        int row = rowBase + w * 16 + (lane >> 2) + part * 8;
        if ((lane & 3) == 0 && row < N) out[row] = partial + sbh2[0];
    }
}

// ---------------------------------------------------------------------------
// Launch: default stream, graph-capturable, no allocation, no sync.
// ---------------------------------------------------------------------------
extern "C" void kernel_launch(void* const* d_in, const int* in_sizes, int n_in,
                              void* d_out, int out_size)
{
    const float*     loc_x = (const float*)d_in[0];
    const float*     evt_x = (const float*)d_in[1];
    const long long* ei    = (const long long*)d_in[2];
    const float*     W_loc = (const float*)d_in[3];
    const float*     b_loc = (const float*)d_in[4];
    const float*     W_evt = (const float*)d_in[5];
    const float*     b_evt = (const float*)d_in[6];
    const float*     W_l   = (const float*)d_in[7];
    const float*     b_l   = (const float*)d_in[8];
    const float*     W_r   = (const float*)d_in[9];
    const float*     W_h1  = (const float*)d_in[10];
    const float*     b_h1  = (const float*)d_in[11];
    const float*     W_h2  = (const float*)d_in[12];
    const float*     b_h2  = (const float*)d_in[13];
    float* out = (float*)d_out;

    int NL = in_sizes[0] / 128;   // 100000
    int NE = in_sizes[1] / 128;   // 200000
    int E  = in_sizes[2] / 2;     // 1000000
    if (NL > MAX_LOC) NL = MAX_LOC;
    if (NE > MAX_EVT) NE = MAX_EVT;

    cudaFuncSetAttribute(proj_mma_kernel,
                         cudaFuncAttributeMaxDynamicSharedMemorySize, PROJ_SMEM);
    cudaFuncSetAttribute(fused_mma_kernel,
                         cudaFuncAttributeMaxDynamicSharedMemorySize, FUSEDM_SMEM);

    int zb = (NL * 16 + 255) / 256;       // zero blocks
    prep_kernel<<<zb + 52, 256>>>(ei, W_loc, W_evt, W_l, W_r, W_h1,
                                  NL * 16, NL, zb);

    int nA = (NL + 127) / 128;            // 782 loc tiles
    int nB = (NE + 127) / 128;            // 1563 evt tiles
    proj_mma_kernel<<<nA + nB, 256, PROJ_SMEM>>>(loc_x, b_loc, NL,
                                                 evt_x, b_evt, NE, nA);

    int groups = (E + 3) / 4;             // 4 edges per 16-thread group
    long sc_threads = (long)groups * 16;
    int sc_blocks = (int)((sc_threads + 255) / 256);
    scatter_kernel<<<sc_blocks, 256>>>(ei, E, NL);

    fused_mma_kernel<<<nA, 256, FUSEDM_SMEM>>>(b_l, b_h1, W_h2, b_h2, out, NL);
}